// round 2
// baseline (speedup 1.0000x reference)
#include <cuda_runtime.h>
#include <math.h>

// Problem constants
#define BB 2
#define SS 4096
#define EE 768
#define HH 12
#define DD 64
#define WW 256
#define ROWS (BB*SS)          // 8192
#define C3 (3*EE)             // 2304
#define E4 (4*EE)             // 3072

// ---------------- scratch (static device allocations) ----------------
__device__ float g_buf_h   [ROWS * EE];   // ln1 out, reused as ln2 out
__device__ float g_buf_qkv [ROWS * C3];
__device__ float g_buf_attn[ROWS * EE];
__device__ float g_buf_x1  [ROWS * EE];
__device__ float g_buf_ff  [ROWS * E4];

// ---------------- LayerNorm ----------------
// one block per row, 256 threads, E=768 (3 elems/thread)
__global__ __launch_bounds__(256)
void ln_kernel(const float* __restrict__ x, const float* __restrict__ g,
               const float* __restrict__ b, float* __restrict__ out)
{
    const int row = blockIdx.x;
    const int tid = threadIdx.x;
    const float* xr = x + (long)row * EE;
    float v0 = xr[tid], v1 = xr[tid + 256], v2 = xr[tid + 512];
    float s  = v0 + v1 + v2;
    float sq = v0*v0 + v1*v1 + v2*v2;

    __shared__ float sh_s[8], sh_q[8];
    #pragma unroll
    for (int o = 16; o > 0; o >>= 1) {
        s  += __shfl_xor_sync(0xffffffffu, s,  o);
        sq += __shfl_xor_sync(0xffffffffu, sq, o);
    }
    const int wid = tid >> 5, lane = tid & 31;
    if (lane == 0) { sh_s[wid] = s; sh_q[wid] = sq; }
    __syncthreads();
    if (wid == 0) {
        s  = (lane < 8) ? sh_s[lane] : 0.f;
        sq = (lane < 8) ? sh_q[lane] : 0.f;
        #pragma unroll
        for (int o = 4; o > 0; o >>= 1) {
            s  += __shfl_xor_sync(0xffffffffu, s,  o);
            sq += __shfl_xor_sync(0xffffffffu, sq, o);
        }
        if (lane == 0) { sh_s[0] = s; sh_q[0] = sq; }
    }
    __syncthreads();
    const float mean = sh_s[0] * (1.f / EE);
    const float var  = sh_q[0] * (1.f / EE) - mean * mean;
    const float inv  = rsqrtf(var + 1e-5f);

    float* orow = out + (long)row * EE;
    orow[tid      ] = (v0 - mean) * inv * g[tid      ] + b[tid      ];
    orow[tid + 256] = (v1 - mean) * inv * g[tid + 256] + b[tid + 256];
    orow[tid + 512] = (v2 - mean) * inv * g[tid + 512] + b[tid + 512];
}

// ---------------- SGEMM: C[M,N] = A[M,K] @ B[K,N] + bias (+residual / gelu) --
// 128x128 tile, BK=8, 256 threads, 8x8 per thread.
// EPI: 0 = +bias   1 = +bias+residual   2 = gelu(+bias)
template<int EPI>
__global__ __launch_bounds__(256)
void sgemm_kernel(const float* __restrict__ A, const float* __restrict__ B,
                  const float* __restrict__ bias, const float* __restrict__ R,
                  float* __restrict__ C, int M, int N, int K)
{
    __shared__ float As[8][128];
    __shared__ float Bs[8][128];

    const int tid = threadIdx.x;
    const int bm = blockIdx.y * 128;
    const int bn = blockIdx.x * 128;

    const int arow = tid >> 1, acol = (tid & 1) * 4;
    const int brow = tid >> 5, bcol = (tid & 31) * 4;

    const float* Ap = A + (long)(bm + arow) * K + acol;
    const float* Bp = B + (long)brow * N + bn + bcol;

    const int tr = (tid >> 4) * 8;
    const int tc = (tid & 15) * 8;

    float acc[8][8] = {};
    float af[8], bf[8];

    for (int k0 = 0; k0 < K; k0 += 8) {
        float4 av = *(const float4*)Ap;
        As[acol + 0][arow] = av.x;
        As[acol + 1][arow] = av.y;
        As[acol + 2][arow] = av.z;
        As[acol + 3][arow] = av.w;
        *(float4*)&Bs[brow][bcol] = *(const float4*)Bp;
        __syncthreads();
        #pragma unroll
        for (int k = 0; k < 8; k++) {
            *(float4*)&af[0] = *(const float4*)&As[k][tr];
            *(float4*)&af[4] = *(const float4*)&As[k][tr + 4];
            *(float4*)&bf[0] = *(const float4*)&Bs[k][tc];
            *(float4*)&bf[4] = *(const float4*)&Bs[k][tc + 4];
            #pragma unroll
            for (int i = 0; i < 8; i++)
                #pragma unroll
                for (int j = 0; j < 8; j++)
                    acc[i][j] += af[i] * bf[j];
        }
        __syncthreads();
        Ap += 8;
        Bp += 8 * (long)N;
    }

    #pragma unroll
    for (int i = 0; i < 8; i++) {
        const long roff = (long)(bm + tr + i) * N + bn + tc;
        #pragma unroll
        for (int j = 0; j < 8; j++) {
            float v = acc[i][j] + bias[bn + tc + j];
            if (EPI == 1) v += R[roff + j];
            if (EPI == 2) v = 0.5f * v * (1.f + erff(v * 0.70710678118654752f));
            C[roff + j] = v;
        }
    }
}

// ---------------- Sliding-window attention ----------------
// grid: (S/128, H, B), 128 threads: one query per thread.
// q and fp32 accumulator live in registers; K/V tiles (64x64) staged in smem.
__global__ __launch_bounds__(128)
void attn_kernel(const float* __restrict__ qkv, float* __restrict__ out)
{
    const int qt = blockIdx.x, h = blockIdx.y, b = blockIdx.z;
    const int qi = qt * 128 + threadIdx.x;

    __shared__ float Kt[64][64];
    __shared__ float Vt[64][64];

    float q[DD];
    const float* qp = qkv + ((long)(b * SS + qi)) * C3 + h * DD;
    #pragma unroll
    for (int d = 0; d < DD; d += 4) {
        float4 v4 = *(const float4*)(qp + d);
        q[d + 0] = v4.x * 0.125f;
        q[d + 1] = v4.y * 0.125f;
        q[d + 2] = v4.z * 0.125f;
        q[d + 3] = v4.w * 0.125f;
    }

    float acc[DD] = {};
    float m = -1e30f, l = 0.f;

    const int kstart = qt * 128 - WW;
    const int r  = threadIdx.x >> 1;
    const int cb = (threadIdx.x & 1) * 32;

    for (int t = 0; t < 10; t++) {
        const int ks = kstart + t * 64;
        const int j = ks + r;
        if (j >= 0 && j < SS) {
            const float* kp = qkv + ((long)(b * SS + j)) * C3 + EE  + h * DD + cb;
            const float* vp = qkv + ((long)(b * SS + j)) * C3 + 2*EE + h * DD + cb;
            #pragma unroll
            for (int c = 0; c < 32; c += 4) {
                *(float4*)&Kt[r][cb + c] = *(const float4*)(kp + c);
                *(float4*)&Vt[r][cb + c] = *(const float4*)(vp + c);
            }
        } else {
            #pragma unroll
            for (int c = 0; c < 32; c += 4) {
                *(float4*)&Kt[r][cb + c] = make_float4(0.f, 0.f, 0.f, 0.f);
                *(float4*)&Vt[r][cb + c] = make_float4(0.f, 0.f, 0.f, 0.f);
            }
        }
        __syncthreads();

        for (int jj = 0; jj < 64; jj++) {
            const int j2 = ks + jj;
            const bool valid = (j2 >= 0) & (j2 < SS) &
                               (j2 >= qi - WW) & (j2 <= qi + WW);
            if (valid) {
                float s = 0.f;
                #pragma unroll
                for (int d = 0; d < DD; d++) s += q[d] * Kt[jj][d];
                if (s > m) {
                    const float c = __expf(m - s);
                    l *= c;
                    #pragma unroll
                    for (int d = 0; d < DD; d++) acc[d] *= c;
                    m = s;
                }
                const float p = __expf(s - m);
                l += p;
                #pragma unroll
                for (int d = 0; d < DD; d++) acc[d] += p * Vt[jj][d];
            }
        }
        __syncthreads();
    }

    const float inv = 1.f / l;
    float* op = out + ((long)(b * SS + qi)) * EE + h * DD;
    #pragma unroll
    for (int d = 0; d < DD; d++) op[d] = acc[d] * inv;
}

// ---------------- launch ----------------
extern "C" void kernel_launch(void* const* d_in, const int* in_sizes, int n_in,
                              void* d_out, int out_size)
{
    const float* x        = (const float*)d_in[0];
    const float* ln1_g    = (const float*)d_in[1];
    const float* ln1_b    = (const float*)d_in[2];
    const float* c_attn_w = (const float*)d_in[3];
    const float* c_attn_b = (const float*)d_in[4];
    const float* c_proj_w = (const float*)d_in[5];
    const float* c_proj_b = (const float*)d_in[6];
    const float* ln2_g    = (const float*)d_in[7];
    const float* ln2_b    = (const float*)d_in[8];
    const float* fc_w     = (const float*)d_in[9];
    const float* fc_b     = (const float*)d_in[10];
    const float* proj2_w  = (const float*)d_in[11];
    const float* proj2_b  = (const float*)d_in[12];
    float* out = (float*)d_out;

    float *h, *qkv, *attn, *x1, *ff;
    cudaGetSymbolAddress((void**)&h,    g_buf_h);
    cudaGetSymbolAddress((void**)&qkv,  g_buf_qkv);
    cudaGetSymbolAddress((void**)&attn, g_buf_attn);
    cudaGetSymbolAddress((void**)&x1,   g_buf_x1);
    cudaGetSymbolAddress((void**)&ff,   g_buf_ff);

    // 1) ln1
    ln_kernel<<<ROWS, 256>>>(x, ln1_g, ln1_b, h);
    // 2) qkv = h @ c_attn_w + c_attn_b  [8192 x 2304]
    sgemm_kernel<0><<<dim3(C3 / 128, ROWS / 128), 256>>>(
        h, c_attn_w, c_attn_b, nullptr, qkv, ROWS, C3, EE);
    // 3) sliding-window attention
    attn_kernel<<<dim3(SS / 128, HH, BB), 128>>>(qkv, attn);
    // 4) x1 = attn @ c_proj_w + c_proj_b + x
    sgemm_kernel<1><<<dim3(EE / 128, ROWS / 128), 256>>>(
        attn, c_proj_w, c_proj_b, x, x1, ROWS, EE, EE);
    // 5) ln2
    ln_kernel<<<ROWS, 256>>>(x1, ln2_g, ln2_b, h);
    // 6) ff = gelu(h @ fc_w + fc_b)  [8192 x 3072]
    sgemm_kernel<2><<<dim3(E4 / 128, ROWS / 128), 256>>>(
        h, fc_w, fc_b, nullptr, ff, ROWS, E4, EE);
    // 7) out = ff @ proj2_w + proj2_b + x1
    sgemm_kernel<1><<<dim3(EE / 128, ROWS / 128), 256>>>(
        ff, proj2_w, proj2_b, x1, out, ROWS, EE, E4);
}

// round 3
// speedup vs baseline: 1.6675x; 1.6675x over previous
#include <cuda_runtime.h>
#include <math.h>
#include <stdint.h>

// Problem constants
#define BB 2
#define SS 4096
#define EE 768
#define HH 12
#define DD 64
#define WW 256
#define ROWS (BB*SS)          // 8192
#define C3 (3*EE)             // 2304
#define E4 (4*EE)             // 3072

// ---------------- scratch (static device allocations) ----------------
__device__ float g_buf_h   [ROWS * EE];
__device__ float g_buf_qkv [ROWS * C3];
__device__ float g_buf_attn[ROWS * EE];
__device__ float g_buf_x1  [ROWS * EE];
__device__ float g_buf_ff  [ROWS * E4];

// ---------------- LayerNorm ----------------
__global__ __launch_bounds__(256)
void ln_kernel(const float* __restrict__ x, const float* __restrict__ g,
               const float* __restrict__ b, float* __restrict__ out)
{
    const int row = blockIdx.x;
    const int tid = threadIdx.x;
    const float* xr = x + (long)row * EE;
    float v0 = xr[tid], v1 = xr[tid + 256], v2 = xr[tid + 512];
    float s  = v0 + v1 + v2;
    float sq = v0*v0 + v1*v1 + v2*v2;

    __shared__ float sh_s[8], sh_q[8];
    #pragma unroll
    for (int o = 16; o > 0; o >>= 1) {
        s  += __shfl_xor_sync(0xffffffffu, s,  o);
        sq += __shfl_xor_sync(0xffffffffu, sq, o);
    }
    const int wid = tid >> 5, lane = tid & 31;
    if (lane == 0) { sh_s[wid] = s; sh_q[wid] = sq; }
    __syncthreads();
    if (wid == 0) {
        s  = (lane < 8) ? sh_s[lane] : 0.f;
        sq = (lane < 8) ? sh_q[lane] : 0.f;
        #pragma unroll
        for (int o = 4; o > 0; o >>= 1) {
            s  += __shfl_xor_sync(0xffffffffu, s,  o);
            sq += __shfl_xor_sync(0xffffffffu, sq, o);
        }
        if (lane == 0) { sh_s[0] = s; sh_q[0] = sq; }
    }
    __syncthreads();
    const float mean = sh_s[0] * (1.f / EE);
    const float var  = sh_q[0] * (1.f / EE) - mean * mean;
    const float inv  = rsqrtf(var + 1e-5f);

    float* orow = out + (long)row * EE;
    orow[tid      ] = (v0 - mean) * inv * g[tid      ] + b[tid      ];
    orow[tid + 256] = (v1 - mean) * inv * g[tid + 256] + b[tid + 256];
    orow[tid + 512] = (v2 - mean) * inv * g[tid + 512] + b[tid + 512];
}

// ---------------- tf32 helpers ----------------
__device__ __forceinline__ uint32_t f2tf32(float v) {
    uint32_t o;
    asm("cvt.rna.tf32.f32 %0, %1;" : "=r"(o) : "f"(v));
    return o;
}

__device__ __forceinline__ void mma_tf32(float c[4], const uint32_t a[4], const uint32_t b[2]) {
    asm volatile(
        "mma.sync.aligned.m16n8k8.row.col.f32.tf32.tf32.f32 "
        "{%0,%1,%2,%3}, {%4,%5,%6,%7}, {%8,%9}, {%0,%1,%2,%3};"
        : "+f"(c[0]), "+f"(c[1]), "+f"(c[2]), "+f"(c[3])
        : "r"(a[0]), "r"(a[1]), "r"(a[2]), "r"(a[3]), "r"(b[0]), "r"(b[1]));
}

// ---------------- TF32 GEMM: C[M,N] = A[M,K] @ B[K,N] + bias (+res/gelu) ----
// 128x128 block tile, BK=16, 256 threads = 8 warps (4x2), warp tile 32x64.
// m16n8k8 tf32 HMMA. Double-buffered smem, reg prefetch, one sync per K-tile.
// EPI: 0 = +bias   1 = +bias+residual   2 = gelu(+bias)
#define ASTR 17
#define BSTR 132
template<int EPI>
__global__ __launch_bounds__(256, 1)
void tgemm_kernel(const float* __restrict__ A, const float* __restrict__ B,
                  const float* __restrict__ bias, const float* __restrict__ R,
                  float* __restrict__ C, int M, int N, int K)
{
    __shared__ uint32_t As[2][128 * ASTR];   // [row][k], stride 17
    __shared__ uint32_t Bs[2][16 * BSTR];    // [k][col], stride 132

    const int tid  = threadIdx.x;
    const int warp = tid >> 5;
    const int lane = tid & 31;
    const int g    = lane >> 2;     // group 0..7
    const int tg   = lane & 3;      // thread-in-group 0..3
    const int wm   = warp >> 1;     // 0..3
    const int wn   = warp & 1;      // 0..1

    const int bm = blockIdx.y * 128;
    const int bn = blockIdx.x * 128;

    // gmem load mapping: A tile 128x16, B tile 16x128, 2x float4 each
    const int arow = tid >> 1,  acol = (tid & 1) * 8;
    const int brow = tid >> 4,  bcol = (tid & 15) * 8;

    const float* Ap = A + (long)(bm + arow) * K + acol;
    const float* Bp = B + (long)brow * N + bn + bcol;

    float4 ra0, ra1, rb0, rb1;

    // load tile 0
    ra0 = *(const float4*)(Ap);
    ra1 = *(const float4*)(Ap + 4);
    rb0 = *(const float4*)(Bp);
    rb1 = *(const float4*)(Bp + 4);

    // store tile 0 to buf 0 (with tf32 rounding)
    {
        uint32_t* a = &As[0][arow * ASTR + acol];
        a[0]=f2tf32(ra0.x); a[1]=f2tf32(ra0.y); a[2]=f2tf32(ra0.z); a[3]=f2tf32(ra0.w);
        a[4]=f2tf32(ra1.x); a[5]=f2tf32(ra1.y); a[6]=f2tf32(ra1.z); a[7]=f2tf32(ra1.w);
        uint32_t* bp = &Bs[0][brow * BSTR + bcol];
        bp[0]=f2tf32(rb0.x); bp[1]=f2tf32(rb0.y); bp[2]=f2tf32(rb0.z); bp[3]=f2tf32(rb0.w);
        bp[4]=f2tf32(rb1.x); bp[5]=f2tf32(rb1.y); bp[6]=f2tf32(rb1.z); bp[7]=f2tf32(rb1.w);
    }
    __syncthreads();

    float acc[2][8][4] = {};
    const int T = K >> 4;   // K/16 tiles

    for (int t = 0; t < T; t++) {
        const int cur = t & 1, nxt = cur ^ 1;
        // prefetch next tile into registers
        if (t + 1 < T) {
            const float* Ap2 = Ap + (t + 1) * 16;
            const float* Bp2 = Bp + (long)(t + 1) * 16 * N;
            ra0 = *(const float4*)(Ap2);
            ra1 = *(const float4*)(Ap2 + 4);
            rb0 = *(const float4*)(Bp2);
            rb1 = *(const float4*)(Bp2 + 4);
        }

        // compute on current buffer: 2 k-steps of 8
        #pragma unroll
        for (int ks = 0; ks < 16; ks += 8) {
            uint32_t af[2][4];
            #pragma unroll
            for (int mi = 0; mi < 2; mi++) {
                const int r = wm * 32 + mi * 16 + g;
                af[mi][0] = As[cur][ r      * ASTR + ks + tg    ];
                af[mi][1] = As[cur][(r + 8) * ASTR + ks + tg    ];
                af[mi][2] = As[cur][ r      * ASTR + ks + tg + 4];
                af[mi][3] = As[cur][(r + 8) * ASTR + ks + tg + 4];
            }
            #pragma unroll
            for (int ni = 0; ni < 8; ni++) {
                uint32_t bf[2];
                const int c = wn * 64 + ni * 8 + g;
                bf[0] = Bs[cur][(ks + tg)     * BSTR + c];
                bf[1] = Bs[cur][(ks + tg + 4) * BSTR + c];
                #pragma unroll
                for (int mi = 0; mi < 2; mi++)
                    mma_tf32(acc[mi][ni], af[mi], bf);
            }
        }

        // store prefetched tile to other buffer
        if (t + 1 < T) {
            uint32_t* a = &As[nxt][arow * ASTR + acol];
            a[0]=f2tf32(ra0.x); a[1]=f2tf32(ra0.y); a[2]=f2tf32(ra0.z); a[3]=f2tf32(ra0.w);
            a[4]=f2tf32(ra1.x); a[5]=f2tf32(ra1.y); a[6]=f2tf32(ra1.z); a[7]=f2tf32(ra1.w);
            uint32_t* bp = &Bs[nxt][brow * BSTR + bcol];
            bp[0]=f2tf32(rb0.x); bp[1]=f2tf32(rb0.y); bp[2]=f2tf32(rb0.z); bp[3]=f2tf32(rb0.w);
            bp[4]=f2tf32(rb1.x); bp[5]=f2tf32(rb1.y); bp[6]=f2tf32(rb1.z); bp[7]=f2tf32(rb1.w);
        }
        __syncthreads();
    }

    // epilogue
    #pragma unroll
    for (int mi = 0; mi < 2; mi++) {
        const int r0 = bm + wm * 32 + mi * 16 + g;
        #pragma unroll
        for (int ni = 0; ni < 8; ni++) {
            const int cn = bn + wn * 64 + ni * 8 + 2 * tg;
            const float bz0 = bias[cn], bz1 = bias[cn + 1];
            float v00 = acc[mi][ni][0] + bz0;
            float v01 = acc[mi][ni][1] + bz1;
            float v10 = acc[mi][ni][2] + bz0;
            float v11 = acc[mi][ni][3] + bz1;
            const long o0 = (long)r0 * N + cn;
            const long o1 = (long)(r0 + 8) * N + cn;
            if (EPI == 1) {
                v00 += R[o0]; v01 += R[o0 + 1];
                v10 += R[o1]; v11 += R[o1 + 1];
            }
            if (EPI == 2) {
                v00 = 0.5f * v00 * (1.f + erff(v00 * 0.70710678118654752f));
                v01 = 0.5f * v01 * (1.f + erff(v01 * 0.70710678118654752f));
                v10 = 0.5f * v10 * (1.f + erff(v10 * 0.70710678118654752f));
                v11 = 0.5f * v11 * (1.f + erff(v11 * 0.70710678118654752f));
            }
            *(float2*)&C[o0] = make_float2(v00, v01);
            *(float2*)&C[o1] = make_float2(v10, v11);
        }
    }
}

// ---------------- Sliding-window attention ----------------
__global__ __launch_bounds__(128)
void attn_kernel(const float* __restrict__ qkv, float* __restrict__ out)
{
    const int qt = blockIdx.x, h = blockIdx.y, b = blockIdx.z;
    const int qi = qt * 128 + threadIdx.x;

    __shared__ float Kt[64][64];
    __shared__ float Vt[64][64];

    float q[DD];
    const float* qp = qkv + ((long)(b * SS + qi)) * C3 + h * DD;
    #pragma unroll
    for (int d = 0; d < DD; d += 4) {
        float4 v4 = *(const float4*)(qp + d);
        q[d + 0] = v4.x * 0.125f;
        q[d + 1] = v4.y * 0.125f;
        q[d + 2] = v4.z * 0.125f;
        q[d + 3] = v4.w * 0.125f;
    }

    float acc[DD] = {};
    float m = -1e30f, l = 0.f;

    const int kstart = qt * 128 - WW;
    const int r  = threadIdx.x >> 1;
    const int cb = (threadIdx.x & 1) * 32;

    for (int t = 0; t < 10; t++) {
        const int ks = kstart + t * 64;
        const int j = ks + r;
        if (j >= 0 && j < SS) {
            const float* kp = qkv + ((long)(b * SS + j)) * C3 + EE  + h * DD + cb;
            const float* vp = qkv + ((long)(b * SS + j)) * C3 + 2*EE + h * DD + cb;
            #pragma unroll
            for (int c = 0; c < 32; c += 4) {
                *(float4*)&Kt[r][cb + c] = *(const float4*)(kp + c);
                *(float4*)&Vt[r][cb + c] = *(const float4*)(vp + c);
            }
        } else {
            #pragma unroll
            for (int c = 0; c < 32; c += 4) {
                *(float4*)&Kt[r][cb + c] = make_float4(0.f, 0.f, 0.f, 0.f);
                *(float4*)&Vt[r][cb + c] = make_float4(0.f, 0.f, 0.f, 0.f);
            }
        }
        __syncthreads();

        for (int jj = 0; jj < 64; jj++) {
            const int j2 = ks + jj;
            const bool valid = (j2 >= 0) & (j2 < SS) &
                               (j2 >= qi - WW) & (j2 <= qi + WW);
            if (valid) {
                float s = 0.f;
                #pragma unroll
                for (int d = 0; d < DD; d++) s += q[d] * Kt[jj][d];
                if (s > m) {
                    const float c = __expf(m - s);
                    l *= c;
                    #pragma unroll
                    for (int d = 0; d < DD; d++) acc[d] *= c;
                    m = s;
                }
                const float p = __expf(s - m);
                l += p;
                #pragma unroll
                for (int d = 0; d < DD; d++) acc[d] += p * Vt[jj][d];
            }
        }
        __syncthreads();
    }

    const float inv = 1.f / l;
    float* op = out + ((long)(b * SS + qi)) * EE + h * DD;
    #pragma unroll
    for (int d = 0; d < DD; d++) op[d] = acc[d] * inv;
}

// ---------------- launch ----------------
extern "C" void kernel_launch(void* const* d_in, const int* in_sizes, int n_in,
                              void* d_out, int out_size)
{
    const float* x        = (const float*)d_in[0];
    const float* ln1_g    = (const float*)d_in[1];
    const float* ln1_b    = (const float*)d_in[2];
    const float* c_attn_w = (const float*)d_in[3];
    const float* c_attn_b = (const float*)d_in[4];
    const float* c_proj_w = (const float*)d_in[5];
    const float* c_proj_b = (const float*)d_in[6];
    const float* ln2_g    = (const float*)d_in[7];
    const float* ln2_b    = (const float*)d_in[8];
    const float* fc_w     = (const float*)d_in[9];
    const float* fc_b     = (const float*)d_in[10];
    const float* proj2_w  = (const float*)d_in[11];
    const float* proj2_b  = (const float*)d_in[12];
    float* out = (float*)d_out;

    float *h, *qkv, *attn, *x1, *ff;
    cudaGetSymbolAddress((void**)&h,    g_buf_h);
    cudaGetSymbolAddress((void**)&qkv,  g_buf_qkv);
    cudaGetSymbolAddress((void**)&attn, g_buf_attn);
    cudaGetSymbolAddress((void**)&x1,   g_buf_x1);
    cudaGetSymbolAddress((void**)&ff,   g_buf_ff);

    ln_kernel<<<ROWS, 256>>>(x, ln1_g, ln1_b, h);
    tgemm_kernel<0><<<dim3(C3 / 128, ROWS / 128), 256>>>(
        h, c_attn_w, c_attn_b, nullptr, qkv, ROWS, C3, EE);
    attn_kernel<<<dim3(SS / 128, HH, BB), 128>>>(qkv, attn);
    tgemm_kernel<1><<<dim3(EE / 128, ROWS / 128), 256>>>(
        attn, c_proj_w, c_proj_b, x, x1, ROWS, EE, EE);
    ln_kernel<<<ROWS, 256>>>(x1, ln2_g, ln2_b, h);
    tgemm_kernel<2><<<dim3(E4 / 128, ROWS / 128), 256>>>(
        h, fc_w, fc_b, nullptr, ff, ROWS, E4, EE);
    tgemm_kernel<1><<<dim3(EE / 128, ROWS / 128), 256>>>(
        ff, proj2_w, proj2_b, x1, out, ROWS, EE, E4);
}

// round 4
// speedup vs baseline: 1.9698x; 1.1813x over previous
#include <cuda_runtime.h>
#include <math.h>
#include <stdint.h>

// Problem constants
#define BB 2
#define SS 4096
#define EE 768
#define HH 12
#define DD 64
#define WW 256
#define ROWS (BB*SS)          // 8192
#define C3 (3*EE)             // 2304
#define E4 (4*EE)             // 3072

// ---------------- scratch (static device allocations) ----------------
__device__ float g_buf_h   [ROWS * EE];
__device__ float g_buf_qkv [ROWS * C3];
__device__ float g_buf_attn[ROWS * EE];
__device__ float g_buf_x1  [ROWS * EE];
__device__ float g_buf_ff  [ROWS * E4];

// ---------------- LayerNorm ----------------
__global__ __launch_bounds__(256)
void ln_kernel(const float* __restrict__ x, const float* __restrict__ g,
               const float* __restrict__ b, float* __restrict__ out)
{
    const int row = blockIdx.x;
    const int tid = threadIdx.x;
    const float* xr = x + (long)row * EE;
    float v0 = xr[tid], v1 = xr[tid + 256], v2 = xr[tid + 512];
    float s  = v0 + v1 + v2;
    float sq = v0*v0 + v1*v1 + v2*v2;

    __shared__ float sh_s[8], sh_q[8];
    #pragma unroll
    for (int o = 16; o > 0; o >>= 1) {
        s  += __shfl_xor_sync(0xffffffffu, s,  o);
        sq += __shfl_xor_sync(0xffffffffu, sq, o);
    }
    const int wid = tid >> 5, lane = tid & 31;
    if (lane == 0) { sh_s[wid] = s; sh_q[wid] = sq; }
    __syncthreads();
    if (wid == 0) {
        s  = (lane < 8) ? sh_s[lane] : 0.f;
        sq = (lane < 8) ? sh_q[lane] : 0.f;
        #pragma unroll
        for (int o = 4; o > 0; o >>= 1) {
            s  += __shfl_xor_sync(0xffffffffu, s,  o);
            sq += __shfl_xor_sync(0xffffffffu, sq, o);
        }
        if (lane == 0) { sh_s[0] = s; sh_q[0] = sq; }
    }
    __syncthreads();
    const float mean = sh_s[0] * (1.f / EE);
    const float var  = sh_q[0] * (1.f / EE) - mean * mean;
    const float inv  = rsqrtf(var + 1e-5f);

    float* orow = out + (long)row * EE;
    orow[tid      ] = (v0 - mean) * inv * g[tid      ] + b[tid      ];
    orow[tid + 256] = (v1 - mean) * inv * g[tid + 256] + b[tid + 256];
    orow[tid + 512] = (v2 - mean) * inv * g[tid + 512] + b[tid + 512];
}

// ---------------- tf32 helpers ----------------
__device__ __forceinline__ uint32_t f2tf32(float v) {
    uint32_t o;
    asm("cvt.rna.tf32.f32 %0, %1;" : "=r"(o) : "f"(v));
    return o;
}

__device__ __forceinline__ void mma_tf32(float c[4], const uint32_t a[4], const uint32_t b[2]) {
    asm volatile(
        "mma.sync.aligned.m16n8k8.row.col.f32.tf32.tf32.f32 "
        "{%0,%1,%2,%3}, {%4,%5,%6,%7}, {%8,%9}, {%0,%1,%2,%3};"
        : "+f"(c[0]), "+f"(c[1]), "+f"(c[2]), "+f"(c[3])
        : "r"(a[0]), "r"(a[1]), "r"(a[2]), "r"(a[3]), "r"(b[0]), "r"(b[1]));
}

__device__ __forceinline__ void cp16(uint32_t saddr, const void* gptr) {
    asm volatile("cp.async.cg.shared.global [%0], [%1], 16;\n"
                 :: "r"(saddr), "l"(gptr));
}
__device__ __forceinline__ void cp_commit() {
    asm volatile("cp.async.commit_group;\n" ::: "memory");
}
__device__ __forceinline__ void cp_wait2() {
    asm volatile("cp.async.wait_group 2;\n" ::: "memory");
}

// ---------------- TF32 GEMM, 4-stage cp.async pipeline --------------------
// 128x128 block tile, BK=16, 256 threads = 8 warps (4x2), warp tile 32x64.
// Raw fp32 staged in smem; cvt.rna.tf32 in the fragment path.
// EPI: 0 = +bias   1 = +bias+residual   2 = gelu(+bias)
#define NSTAGE 4
#define ASTR 20            // A smem row stride (floats): conflict-free frag loads
#define BSTR 132           // B smem row stride
#define ASZ (128 * ASTR)   // 2560 floats per stage
#define BSZ (16 * BSTR)    // 2112 floats per stage
#define GEMM_SMEM (NSTAGE * (ASZ + BSZ) * 4)   // 74752 bytes

template<int EPI>
__global__ __launch_bounds__(256, 1)
void tgemm_kernel(const float* __restrict__ A, const float* __restrict__ B,
                  const float* __restrict__ bias, const float* __restrict__ R,
                  float* __restrict__ C, int M, int N, int K)
{
    extern __shared__ float sm[];
    float* AsBase = sm;                    // NSTAGE * ASZ
    float* BsBase = sm + NSTAGE * ASZ;     // NSTAGE * BSZ

    const int tid  = threadIdx.x;
    const int warp = tid >> 5;
    const int lane = tid & 31;
    const int g    = lane >> 2;
    const int tg   = lane & 3;
    const int wm   = warp >> 1;
    const int wn   = warp & 1;

    const int bm = blockIdx.y * 128;
    const int bn = blockIdx.x * 128;

    // cp.async mappings
    const int arow = tid >> 1, ak = (tid & 1) * 8;      // A: 128x16, 2x16B/thread
    const int brow = tid >> 4, bc = (tid & 15) * 8;     // B: 16x128, 2x16B/thread

    const float* gA = A + (long)(bm + arow) * K + ak;
    const float* gB = B + (long)brow * N + bn + bc;

    const uint32_t sA0 = (uint32_t)__cvta_generic_to_shared(AsBase) + (arow * ASTR + ak) * 4;
    const uint32_t sB0 = (uint32_t)__cvta_generic_to_shared(BsBase) + (brow * BSTR + bc) * 4;

    const int T = K >> 4;

    // prologue: issue stages 0..2
    #pragma unroll
    for (int s = 0; s < NSTAGE - 1; s++) {
        const uint32_t sa = sA0 + s * ASZ * 4;
        const uint32_t sb = sB0 + s * BSZ * 4;
        cp16(sa,      gA + s * 16);
        cp16(sa + 16, gA + s * 16 + 4);
        cp16(sb,      gB + (long)s * 16 * N);
        cp16(sb + 16, gB + (long)s * 16 * N + 4);
        cp_commit();
    }

    float acc[2][8][4] = {};

    for (int t = 0; t < T; t++) {
        cp_wait2();
        __syncthreads();

        // issue stage t+3 (overwrites buffer computed at t-1; safe after sync)
        if (t + NSTAGE - 1 < T) {
            const int s = t + NSTAGE - 1;
            const int bufi = s & (NSTAGE - 1);
            const uint32_t sa = sA0 + bufi * ASZ * 4;
            const uint32_t sb = sB0 + bufi * BSZ * 4;
            cp16(sa,      gA + s * 16);
            cp16(sa + 16, gA + s * 16 + 4);
            cp16(sb,      gB + (long)s * 16 * N);
            cp16(sb + 16, gB + (long)s * 16 * N + 4);
        }
        cp_commit();

        const float* As = AsBase + (t & (NSTAGE - 1)) * ASZ;
        const float* Bs = BsBase + (t & (NSTAGE - 1)) * BSZ;

        #pragma unroll
        for (int ks = 0; ks < 16; ks += 8) {
            uint32_t af[2][4];
            #pragma unroll
            for (int mi = 0; mi < 2; mi++) {
                const int r = wm * 32 + mi * 16 + g;
                af[mi][0] = f2tf32(As[ r      * ASTR + ks + tg    ]);
                af[mi][1] = f2tf32(As[(r + 8) * ASTR + ks + tg    ]);
                af[mi][2] = f2tf32(As[ r      * ASTR + ks + tg + 4]);
                af[mi][3] = f2tf32(As[(r + 8) * ASTR + ks + tg + 4]);
            }
            #pragma unroll
            for (int ni = 0; ni < 8; ni++) {
                uint32_t bf[2];
                const int c = wn * 64 + ni * 8 + g;
                bf[0] = f2tf32(Bs[(ks + tg)     * BSTR + c]);
                bf[1] = f2tf32(Bs[(ks + tg + 4) * BSTR + c]);
                #pragma unroll
                for (int mi = 0; mi < 2; mi++)
                    mma_tf32(acc[mi][ni], af[mi], bf);
            }
        }
        __syncthreads();
    }

    // epilogue
    #pragma unroll
    for (int mi = 0; mi < 2; mi++) {
        const int r0 = bm + wm * 32 + mi * 16 + g;
        #pragma unroll
        for (int ni = 0; ni < 8; ni++) {
            const int cn = bn + wn * 64 + ni * 8 + 2 * tg;
            const float bz0 = bias[cn], bz1 = bias[cn + 1];
            float v00 = acc[mi][ni][0] + bz0;
            float v01 = acc[mi][ni][1] + bz1;
            float v10 = acc[mi][ni][2] + bz0;
            float v11 = acc[mi][ni][3] + bz1;
            const long o0 = (long)r0 * N + cn;
            const long o1 = (long)(r0 + 8) * N + cn;
            if (EPI == 1) {
                v00 += R[o0]; v01 += R[o0 + 1];
                v10 += R[o1]; v11 += R[o1 + 1];
            }
            if (EPI == 2) {
                v00 = 0.5f * v00 * (1.f + erff(v00 * 0.70710678118654752f));
                v01 = 0.5f * v01 * (1.f + erff(v01 * 0.70710678118654752f));
                v10 = 0.5f * v10 * (1.f + erff(v10 * 0.70710678118654752f));
                v11 = 0.5f * v11 * (1.f + erff(v11 * 0.70710678118654752f));
            }
            *(float2*)&C[o0] = make_float2(v00, v01);
            *(float2*)&C[o1] = make_float2(v10, v11);
        }
    }
}

// ---------------- Sliding-window attention ----------------
__global__ __launch_bounds__(128)
void attn_kernel(const float* __restrict__ qkv, float* __restrict__ out)
{
    const int qt = blockIdx.x, h = blockIdx.y, b = blockIdx.z;
    const int qi = qt * 128 + threadIdx.x;

    __shared__ float Kt[64][64];
    __shared__ float Vt[64][64];

    float q[DD];
    const float* qp = qkv + ((long)(b * SS + qi)) * C3 + h * DD;
    #pragma unroll
    for (int d = 0; d < DD; d += 4) {
        float4 v4 = *(const float4*)(qp + d);
        q[d + 0] = v4.x * 0.125f;
        q[d + 1] = v4.y * 0.125f;
        q[d + 2] = v4.z * 0.125f;
        q[d + 3] = v4.w * 0.125f;
    }

    float acc[DD] = {};
    float m = -1e30f, l = 0.f;

    const int kstart = qt * 128 - WW;
    const int r  = threadIdx.x >> 1;
    const int cb = (threadIdx.x & 1) * 32;

    for (int t = 0; t < 10; t++) {
        const int ks = kstart + t * 64;
        const int j = ks + r;
        if (j >= 0 && j < SS) {
            const float* kp = qkv + ((long)(b * SS + j)) * C3 + EE  + h * DD + cb;
            const float* vp = qkv + ((long)(b * SS + j)) * C3 + 2*EE + h * DD + cb;
            #pragma unroll
            for (int c = 0; c < 32; c += 4) {
                *(float4*)&Kt[r][cb + c] = *(const float4*)(kp + c);
                *(float4*)&Vt[r][cb + c] = *(const float4*)(vp + c);
            }
        } else {
            #pragma unroll
            for (int c = 0; c < 32; c += 4) {
                *(float4*)&Kt[r][cb + c] = make_float4(0.f, 0.f, 0.f, 0.f);
                *(float4*)&Vt[r][cb + c] = make_float4(0.f, 0.f, 0.f, 0.f);
            }
        }
        __syncthreads();

        for (int jj = 0; jj < 64; jj++) {
            const int j2 = ks + jj;
            const bool valid = (j2 >= 0) & (j2 < SS) &
                               (j2 >= qi - WW) & (j2 <= qi + WW);
            if (valid) {
                float s = 0.f;
                #pragma unroll
                for (int d = 0; d < DD; d++) s += q[d] * Kt[jj][d];
                if (s > m) {
                    const float c = __expf(m - s);
                    l *= c;
                    #pragma unroll
                    for (int d = 0; d < DD; d++) acc[d] *= c;
                    m = s;
                }
                const float p = __expf(s - m);
                l += p;
                #pragma unroll
                for (int d = 0; d < DD; d++) acc[d] += p * Vt[jj][d];
            }
        }
        __syncthreads();
    }

    const float inv = 1.f / l;
    float* op = out + ((long)(b * SS + qi)) * EE + h * DD;
    #pragma unroll
    for (int d = 0; d < DD; d++) op[d] = acc[d] * inv;
}

// ---------------- launch ----------------
extern "C" void kernel_launch(void* const* d_in, const int* in_sizes, int n_in,
                              void* d_out, int out_size)
{
    const float* x        = (const float*)d_in[0];
    const float* ln1_g    = (const float*)d_in[1];
    const float* ln1_b    = (const float*)d_in[2];
    const float* c_attn_w = (const float*)d_in[3];
    const float* c_attn_b = (const float*)d_in[4];
    const float* c_proj_w = (const float*)d_in[5];
    const float* c_proj_b = (const float*)d_in[6];
    const float* ln2_g    = (const float*)d_in[7];
    const float* ln2_b    = (const float*)d_in[8];
    const float* fc_w     = (const float*)d_in[9];
    const float* fc_b     = (const float*)d_in[10];
    const float* proj2_w  = (const float*)d_in[11];
    const float* proj2_b  = (const float*)d_in[12];
    float* out = (float*)d_out;

    float *h, *qkv, *attn, *x1, *ff;
    cudaGetSymbolAddress((void**)&h,    g_buf_h);
    cudaGetSymbolAddress((void**)&qkv,  g_buf_qkv);
    cudaGetSymbolAddress((void**)&attn, g_buf_attn);
    cudaGetSymbolAddress((void**)&x1,   g_buf_x1);
    cudaGetSymbolAddress((void**)&ff,   g_buf_ff);

    cudaFuncSetAttribute(tgemm_kernel<0>, cudaFuncAttributeMaxDynamicSharedMemorySize, GEMM_SMEM);
    cudaFuncSetAttribute(tgemm_kernel<1>, cudaFuncAttributeMaxDynamicSharedMemorySize, GEMM_SMEM);
    cudaFuncSetAttribute(tgemm_kernel<2>, cudaFuncAttributeMaxDynamicSharedMemorySize, GEMM_SMEM);

    ln_kernel<<<ROWS, 256>>>(x, ln1_g, ln1_b, h);
    tgemm_kernel<0><<<dim3(C3 / 128, ROWS / 128), 256, GEMM_SMEM>>>(
        h, c_attn_w, c_attn_b, nullptr, qkv, ROWS, C3, EE);
    attn_kernel<<<dim3(SS / 128, HH, BB), 128>>>(qkv, attn);
    tgemm_kernel<1><<<dim3(EE / 128, ROWS / 128), 256, GEMM_SMEM>>>(
        attn, c_proj_w, c_proj_b, x, x1, ROWS, EE, EE);
    ln_kernel<<<ROWS, 256>>>(x1, ln2_g, ln2_b, h);
    tgemm_kernel<2><<<dim3(E4 / 128, ROWS / 128), 256, GEMM_SMEM>>>(
        h, fc_w, fc_b, nullptr, ff, ROWS, E4, EE);
    tgemm_kernel<1><<<dim3(EE / 128, ROWS / 128), 256, GEMM_SMEM>>>(
        ff, proj2_w, proj2_b, x1, out, ROWS, EE, E4);
}

// round 6
// speedup vs baseline: 2.0769x; 1.0544x over previous
#include <cuda_runtime.h>
#include <math.h>
#include <stdint.h>

// Problem constants
#define BB 2
#define SS 4096
#define EE 768
#define HH 12
#define DD 64
#define WW 256
#define ROWS (BB*SS)          // 8192
#define C3 (3*EE)             // 2304
#define E4 (4*EE)             // 3072

// ---------------- scratch (static device allocations) ----------------
__device__ float g_buf_h   [ROWS * EE];
__device__ float g_buf_qkv [ROWS * C3];
__device__ float g_buf_attn[ROWS * EE];
__device__ float g_buf_x1  [ROWS * EE];
__device__ float g_buf_ff  [ROWS * E4];

// ---------------- LayerNorm ----------------
__global__ __launch_bounds__(256)
void ln_kernel(const float* __restrict__ x, const float* __restrict__ g,
               const float* __restrict__ b, float* __restrict__ out)
{
    const int row = blockIdx.x;
    const int tid = threadIdx.x;
    const float* xr = x + (long)row * EE;
    float v0 = xr[tid], v1 = xr[tid + 256], v2 = xr[tid + 512];
    float s  = v0 + v1 + v2;
    float sq = v0*v0 + v1*v1 + v2*v2;

    __shared__ float sh_s[8], sh_q[8];
    #pragma unroll
    for (int o = 16; o > 0; o >>= 1) {
        s  += __shfl_xor_sync(0xffffffffu, s,  o);
        sq += __shfl_xor_sync(0xffffffffu, sq, o);
    }
    const int wid = tid >> 5, lane = tid & 31;
    if (lane == 0) { sh_s[wid] = s; sh_q[wid] = sq; }
    __syncthreads();
    if (wid == 0) {
        s  = (lane < 8) ? sh_s[lane] : 0.f;
        sq = (lane < 8) ? sh_q[lane] : 0.f;
        #pragma unroll
        for (int o = 4; o > 0; o >>= 1) {
            s  += __shfl_xor_sync(0xffffffffu, s,  o);
            sq += __shfl_xor_sync(0xffffffffu, sq, o);
        }
        if (lane == 0) { sh_s[0] = s; sh_q[0] = sq; }
    }
    __syncthreads();
    const float mean = sh_s[0] * (1.f / EE);
    const float var  = sh_q[0] * (1.f / EE) - mean * mean;
    const float inv  = rsqrtf(var + 1e-5f);

    float* orow = out + (long)row * EE;
    orow[tid      ] = (v0 - mean) * inv * g[tid      ] + b[tid      ];
    orow[tid + 256] = (v1 - mean) * inv * g[tid + 256] + b[tid + 256];
    orow[tid + 512] = (v2 - mean) * inv * g[tid + 512] + b[tid + 512];
}

// ---------------- mma helpers ----------------
// tf32 HMMA reads the high 19 bits of each 32-bit reg: raw fp32 in = implicit
// truncation to tf32 (RZ). No explicit cvt needed.
__device__ __forceinline__ void mma_tf32(float c[4], const uint32_t a[4], const uint32_t b[2]) {
    asm volatile(
        "mma.sync.aligned.m16n8k8.row.col.f32.tf32.tf32.f32 "
        "{%0,%1,%2,%3}, {%4,%5,%6,%7}, {%8,%9}, {%0,%1,%2,%3};"
        : "+f"(c[0]), "+f"(c[1]), "+f"(c[2]), "+f"(c[3])
        : "r"(a[0]), "r"(a[1]), "r"(a[2]), "r"(a[3]), "r"(b[0]), "r"(b[1]));
}

__device__ __forceinline__ void cp16(uint32_t saddr, const void* gptr) {
    asm volatile("cp.async.cg.shared.global [%0], [%1], 16;\n"
                 :: "r"(saddr), "l"(gptr));
}
__device__ __forceinline__ void cp_commit() {
    asm volatile("cp.async.commit_group;\n" ::: "memory");
}
__device__ __forceinline__ void cp_wait2() {
    asm volatile("cp.async.wait_group 2;\n" ::: "memory");
}

// ---------------- TF32 GEMM, 4-stage cp.async pipeline --------------------
// 128x256 block tile, BK=16, 512 threads = 16 warps (4x4), warp tile 32x64.
// Raw fp32 in smem + registers; HW truncates to tf32 inside the MMA.
// One __syncthreads per k-tile. Conflict-free smem strides (A:20, B:264).
// EPI: 0 = +bias   1 = +bias+residual   2 = gelu(+bias)
#define NSTAGE 4
#define ASTR 20            // A smem row stride (floats)
#define BSTR 264           // B smem row stride (floats): (8*tg+g) bank map
#define ASZ (128 * ASTR)   // 2560 floats per stage
#define BSZ (16 * BSTR)    // 4224 floats per stage
#define GEMM_SMEM (NSTAGE * (ASZ + BSZ) * 4)   // 108544 bytes
#define BN 256

template<int EPI>
__global__ __launch_bounds__(512, 1)
void tgemm_kernel(const float* __restrict__ A, const float* __restrict__ B,
                  const float* __restrict__ bias, const float* __restrict__ R,
                  float* __restrict__ C, int M, int N, int K)
{
    extern __shared__ float sm[];
    float* AsBase = sm;
    float* BsBase = sm + NSTAGE * ASZ;

    const int tid  = threadIdx.x;
    const int warp = tid >> 5;
    const int lane = tid & 31;
    const int g    = lane >> 2;
    const int tg   = lane & 3;
    const int wm   = warp >> 2;   // 0..3 over M
    const int wn   = warp & 3;    // 0..3 over N

    const int bm = blockIdx.y * 128;
    const int bn = blockIdx.x * BN;

    // cp.async mappings (512 threads)
    const int arow = tid >> 2, ak = (tid & 3) * 4;      // A: 128x16, 1x16B/thread
    const int brow = tid >> 5, bc = (tid & 31) * 8;     // B: 16x256, 2x16B/thread

    const float* gA = A + (long)(bm + arow) * K + ak;
    const float* gB = B + (long)brow * N + bn + bc;

    const uint32_t sA0 = (uint32_t)__cvta_generic_to_shared(AsBase) + (arow * ASTR + ak) * 4;
    const uint32_t sB0 = (uint32_t)__cvta_generic_to_shared(BsBase) + (brow * BSTR + bc) * 4;

    const int T = K >> 4;

    // prologue: issue stages 0..2
    #pragma unroll
    for (int s = 0; s < NSTAGE - 1; s++) {
        const uint32_t sa = sA0 + s * ASZ * 4;
        const uint32_t sb = sB0 + s * BSZ * 4;
        cp16(sa,      gA + s * 16);
        cp16(sb,      gB + (long)s * 16 * N);
        cp16(sb + 16, gB + (long)s * 16 * N + 4);
        cp_commit();
    }

    float acc[2][8][4] = {};

    for (int t = 0; t < T; t++) {
        cp_wait2();
        __syncthreads();

        // issue stage t+3 into buffer (t+3)&3 (== buffer of t-1, done per barrier)
        if (t + NSTAGE - 1 < T) {
            const int s = t + NSTAGE - 1;
            const int bufi = s & (NSTAGE - 1);
            const uint32_t sa = sA0 + bufi * ASZ * 4;
            const uint32_t sb = sB0 + bufi * BSZ * 4;
            cp16(sa,      gA + s * 16);
            cp16(sb,      gB + (long)s * 16 * N);
            cp16(sb + 16, gB + (long)s * 16 * N + 4);
        }
        cp_commit();

        const uint32_t* As = (const uint32_t*)(AsBase + (t & (NSTAGE - 1)) * ASZ);
        const uint32_t* Bs = (const uint32_t*)(BsBase + (t & (NSTAGE - 1)) * BSZ);

        #pragma unroll
        for (int ks = 0; ks < 16; ks += 8) {
            uint32_t af[2][4];
            #pragma unroll
            for (int mi = 0; mi < 2; mi++) {
                const int r = wm * 32 + mi * 16 + g;
                af[mi][0] = As[ r      * ASTR + ks + tg    ];
                af[mi][1] = As[(r + 8) * ASTR + ks + tg    ];
                af[mi][2] = As[ r      * ASTR + ks + tg + 4];
                af[mi][3] = As[(r + 8) * ASTR + ks + tg + 4];
            }
            #pragma unroll
            for (int ni = 0; ni < 8; ni++) {
                uint32_t bf[2];
                const int c = wn * 64 + ni * 8 + g;
                bf[0] = Bs[(ks + tg)     * BSTR + c];
                bf[1] = Bs[(ks + tg + 4) * BSTR + c];
                #pragma unroll
                for (int mi = 0; mi < 2; mi++)
                    mma_tf32(acc[mi][ni], af[mi], bf);
            }
        }
        // no bottom barrier: top wait+sync of iteration t+1 protects buffer reuse
    }

    // epilogue
    #pragma unroll
    for (int mi = 0; mi < 2; mi++) {
        const int r0 = bm + wm * 32 + mi * 16 + g;
        #pragma unroll
        for (int ni = 0; ni < 8; ni++) {
            const int cn = bn + wn * 64 + ni * 8 + 2 * tg;
            const float bz0 = bias[cn], bz1 = bias[cn + 1];
            float v00 = acc[mi][ni][0] + bz0;
            float v01 = acc[mi][ni][1] + bz1;
            float v10 = acc[mi][ni][2] + bz0;
            float v11 = acc[mi][ni][3] + bz1;
            const long o0 = (long)r0 * N + cn;
            const long o1 = (long)(r0 + 8) * N + cn;
            if (EPI == 1) {
                v00 += R[o0]; v01 += R[o0 + 1];
                v10 += R[o1]; v11 += R[o1 + 1];
            }
            if (EPI == 2) {
                v00 = 0.5f * v00 * (1.f + erff(v00 * 0.70710678118654752f));
                v01 = 0.5f * v01 * (1.f + erff(v01 * 0.70710678118654752f));
                v10 = 0.5f * v10 * (1.f + erff(v10 * 0.70710678118654752f));
                v11 = 0.5f * v11 * (1.f + erff(v11 * 0.70710678118654752f));
            }
            *(float2*)&C[o0] = make_float2(v00, v01);
            *(float2*)&C[o1] = make_float2(v10, v11);
        }
    }
}

// ---------------- Sliding-window attention ----------------
__global__ __launch_bounds__(128)
void attn_kernel(const float* __restrict__ qkv, float* __restrict__ out)
{
    const int qt = blockIdx.x, h = blockIdx.y, b = blockIdx.z;
    const int qi = qt * 128 + threadIdx.x;

    __shared__ float Kt[64][64];
    __shared__ float Vt[64][64];

    float q[DD];
    const float* qp = qkv + ((long)(b * SS + qi)) * C3 + h * DD;
    #pragma unroll
    for (int d = 0; d < DD; d += 4) {
        float4 v4 = *(const float4*)(qp + d);
        q[d + 0] = v4.x * 0.125f;
        q[d + 1] = v4.y * 0.125f;
        q[d + 2] = v4.z * 0.125f;
        q[d + 3] = v4.w * 0.125f;
    }

    float acc[DD] = {};
    float m = -1e30f, l = 0.f;

    const int kstart = qt * 128 - WW;
    const int r  = threadIdx.x >> 1;
    const int cb = (threadIdx.x & 1) * 32;

    for (int t = 0; t < 10; t++) {
        const int ks = kstart + t * 64;
        const int j = ks + r;
        if (j >= 0 && j < SS) {
            const float* kp = qkv + ((long)(b * SS + j)) * C3 + EE  + h * DD + cb;
            const float* vp = qkv + ((long)(b * SS + j)) * C3 + 2*EE + h * DD + cb;
            #pragma unroll
            for (int c = 0; c < 32; c += 4) {
                *(float4*)&Kt[r][cb + c] = *(const float4*)(kp + c);
                *(float4*)&Vt[r][cb + c] = *(const float4*)(vp + c);
            }
        } else {
            #pragma unroll
            for (int c = 0; c < 32; c += 4) {
                *(float4*)&Kt[r][cb + c] = make_float4(0.f, 0.f, 0.f, 0.f);
                *(float4*)&Vt[r][cb + c] = make_float4(0.f, 0.f, 0.f, 0.f);
            }
        }
        __syncthreads();

        for (int jj = 0; jj < 64; jj++) {
            const int j2 = ks + jj;
            const bool valid = (j2 >= 0) & (j2 < SS) &
                               (j2 >= qi - WW) & (j2 <= qi + WW);
            if (valid) {
                float s = 0.f;
                #pragma unroll
                for (int d = 0; d < DD; d++) s += q[d] * Kt[jj][d];
                if (s > m) {
                    const float c = __expf(m - s);
                    l *= c;
                    #pragma unroll
                    for (int d = 0; d < DD; d++) acc[d] *= c;
                    m = s;
                }
                const float p = __expf(s - m);
                l += p;
                #pragma unroll
                for (int d = 0; d < DD; d++) acc[d] += p * Vt[jj][d];
            }
        }
        __syncthreads();
    }

    const float inv = 1.f / l;
    float* op = out + ((long)(b * SS + qi)) * EE + h * DD;
    #pragma unroll
    for (int d = 0; d < DD; d++) op[d] = acc[d] * inv;
}

// ---------------- launch ----------------
extern "C" void kernel_launch(void* const* d_in, const int* in_sizes, int n_in,
                              void* d_out, int out_size)
{
    const float* x        = (const float*)d_in[0];
    const float* ln1_g    = (const float*)d_in[1];
    const float* ln1_b    = (const float*)d_in[2];
    const float* c_attn_w = (const float*)d_in[3];
    const float* c_attn_b = (const float*)d_in[4];
    const float* c_proj_w = (const float*)d_in[5];
    const float* c_proj_b = (const float*)d_in[6];
    const float* ln2_g    = (const float*)d_in[7];
    const float* ln2_b    = (const float*)d_in[8];
    const float* fc_w     = (const float*)d_in[9];
    const float* fc_b     = (const float*)d_in[10];
    const float* proj2_w  = (const float*)d_in[11];
    const float* proj2_b  = (const float*)d_in[12];
    float* out = (float*)d_out;

    float *h, *qkv, *attn, *x1, *ff;
    cudaGetSymbolAddress((void**)&h,    g_buf_h);
    cudaGetSymbolAddress((void**)&qkv,  g_buf_qkv);
    cudaGetSymbolAddress((void**)&attn, g_buf_attn);
    cudaGetSymbolAddress((void**)&x1,   g_buf_x1);
    cudaGetSymbolAddress((void**)&ff,   g_buf_ff);

    cudaFuncSetAttribute(tgemm_kernel<0>, cudaFuncAttributeMaxDynamicSharedMemorySize, GEMM_SMEM);
    cudaFuncSetAttribute(tgemm_kernel<1>, cudaFuncAttributeMaxDynamicSharedMemorySize, GEMM_SMEM);
    cudaFuncSetAttribute(tgemm_kernel<2>, cudaFuncAttributeMaxDynamicSharedMemorySize, GEMM_SMEM);

    ln_kernel<<<ROWS, 256>>>(x, ln1_g, ln1_b, h);
    tgemm_kernel<0><<<dim3(C3 / BN, ROWS / 128), 512, GEMM_SMEM>>>(
        h, c_attn_w, c_attn_b, nullptr, qkv, ROWS, C3, EE);
    attn_kernel<<<dim3(SS / 128, HH, BB), 128>>>(qkv, attn);
    tgemm_kernel<1><<<dim3(EE / BN, ROWS / 128), 512, GEMM_SMEM>>>(
        attn, c_proj_w, c_proj_b, x, x1, ROWS, EE, EE);
    ln_kernel<<<ROWS, 256>>>(x1, ln2_g, ln2_b, h);
    tgemm_kernel<2><<<dim3(E4 / BN, ROWS / 128), 512, GEMM_SMEM>>>(
        h, fc_w, fc_b, nullptr, ff, ROWS, E4, EE);
    tgemm_kernel<1><<<dim3(EE / BN, ROWS / 128), 512, GEMM_SMEM>>>(
        ff, proj2_w, proj2_b, x1, out, ROWS, EE, E4);
}

// round 8
// speedup vs baseline: 2.9022x; 1.3973x over previous
#include <cuda_runtime.h>
#include <cuda_fp16.h>
#include <math.h>
#include <stdint.h>

// Problem constants
#define BB 2
#define SS 4096
#define EE 768
#define HH 12
#define DD 64
#define WW 256
#define ROWS (BB*SS)          // 8192
#define C3 (3*EE)             // 2304
#define E4 (4*EE)             // 3072

// ---------------- scratch (static device allocations) ----------------
__device__ __half g_buf_h   [ROWS * EE];   // LN outputs (GEMM A input)
__device__ __half g_buf_qkv [ROWS * C3];
__device__ __half g_buf_attn[ROWS * EE];
__device__ float  g_buf_x1  [ROWS * EE];   // residual stream stays fp32
__device__ __half g_buf_ff  [ROWS * E4];
// transposed fp16 weights [N,K] row-major (K contiguous)
__device__ __half g_wT_attn [C3 * EE];
__device__ __half g_wT_proj [EE * EE];
__device__ __half g_wT_fc   [E4 * EE];
__device__ __half g_wT_proj2[EE * E4];

// ---------------- asm helpers ----------------
__device__ __forceinline__ void mma_f16(float c[4], const uint32_t a[4],
                                        uint32_t b0, uint32_t b1) {
    asm volatile(
        "mma.sync.aligned.m16n8k16.row.col.f32.f16.f16.f32 "
        "{%0,%1,%2,%3}, {%4,%5,%6,%7}, {%8,%9}, {%0,%1,%2,%3};"
        : "+f"(c[0]), "+f"(c[1]), "+f"(c[2]), "+f"(c[3])
        : "r"(a[0]), "r"(a[1]), "r"(a[2]), "r"(a[3]), "r"(b0), "r"(b1));
}

__device__ __forceinline__ void ldsm4(uint32_t r[4], uint32_t addr) {
    asm volatile("ldmatrix.sync.aligned.m8n8.x4.shared.b16 {%0,%1,%2,%3}, [%4];"
                 : "=r"(r[0]), "=r"(r[1]), "=r"(r[2]), "=r"(r[3]) : "r"(addr));
}

__device__ __forceinline__ void cp16(uint32_t saddr, const void* gptr) {
    asm volatile("cp.async.cg.shared.global [%0], [%1], 16;\n"
                 :: "r"(saddr), "l"(gptr));
}
__device__ __forceinline__ void cp_commit() {
    asm volatile("cp.async.commit_group;\n" ::: "memory");
}

// ---------------- LayerNorm (fp32 in, fp16 out) ----------------
__global__ __launch_bounds__(256)
void ln_kernel(const float* __restrict__ x, const float* __restrict__ g,
               const float* __restrict__ b, __half* __restrict__ out)
{
    const int row = blockIdx.x;
    const int tid = threadIdx.x;
    const float* xr = x + (long)row * EE;
    float v0 = xr[tid], v1 = xr[tid + 256], v2 = xr[tid + 512];
    float s  = v0 + v1 + v2;
    float sq = v0*v0 + v1*v1 + v2*v2;

    __shared__ float sh_s[8], sh_q[8];
    #pragma unroll
    for (int o = 16; o > 0; o >>= 1) {
        s  += __shfl_xor_sync(0xffffffffu, s,  o);
        sq += __shfl_xor_sync(0xffffffffu, sq, o);
    }
    const int wid = tid >> 5, lane = tid & 31;
    if (lane == 0) { sh_s[wid] = s; sh_q[wid] = sq; }
    __syncthreads();
    if (wid == 0) {
        s  = (lane < 8) ? sh_s[lane] : 0.f;
        sq = (lane < 8) ? sh_q[lane] : 0.f;
        #pragma unroll
        for (int o = 4; o > 0; o >>= 1) {
            s  += __shfl_xor_sync(0xffffffffu, s,  o);
            sq += __shfl_xor_sync(0xffffffffu, sq, o);
        }
        if (lane == 0) { sh_s[0] = s; sh_q[0] = sq; }
    }
    __syncthreads();
    const float mean = sh_s[0] * (1.f / EE);
    const float var  = sh_q[0] * (1.f / EE) - mean * mean;
    const float inv  = rsqrtf(var + 1e-5f);

    __half* orow = out + (long)row * EE;
    orow[tid      ] = __float2half_rn((v0 - mean) * inv * g[tid      ] + b[tid      ]);
    orow[tid + 256] = __float2half_rn((v1 - mean) * inv * g[tid + 256] + b[tid + 256]);
    orow[tid + 512] = __float2half_rn((v2 - mean) * inv * g[tid + 512] + b[tid + 512]);
}

// ---------------- weight transpose+convert: in fp32 [K,N] -> out fp16 [N,K] --
__global__ __launch_bounds__(256)
void transpose_kernel(const float* __restrict__ in, __half* __restrict__ out,
                      int K, int N)
{
    __shared__ float tile[32][33];
    const int bx = blockIdx.x * 32;   // N
    const int by = blockIdx.y * 32;   // K
    const int tx = threadIdx.x, ty = threadIdx.y;
    #pragma unroll
    for (int i = ty; i < 32; i += 8)
        tile[i][tx] = in[(long)(by + i) * N + bx + tx];
    __syncthreads();
    #pragma unroll
    for (int i = ty; i < 32; i += 8)
        out[(long)(bx + i) * K + by + tx] = __float2half_rn(tile[tx][i]);
}

// ---------------- fp16 HMMA GEMM -----------------------------------------
// C[M,N] = A[M,K] @ Bt[N,K]^T + bias (+res / gelu)
// 128x256 tile, BK=32, 512 threads (16 warps 4x4, warp tile 32x64),
// 4-stage cp.async, XOR-swizzled smem, ldmatrix fragments, m16n8k16 f16.
// EPI: 0 = +bias -> half   1 = +bias+res(fp32) -> float   2 = gelu -> half
#define BK 32
#define ASTG (128 * 64)          // A stage: 128 rows x 64B
#define BSTG (256 * 64)          // B stage: 256 rows x 64B
#define STG  (ASTG + BSTG)       // 24576 B
#define NST  4
#define HG_SMEM (NST * STG)      // 98304 B

template<int EPI>
__global__ __launch_bounds__(512, 1)
void hgemm(const __half* __restrict__ A, const __half* __restrict__ Bt,
           const float* __restrict__ bias, const float* __restrict__ R,
           void* __restrict__ Cout, int M, int N, int K)
{
    extern __shared__ char smem[];
    const uint32_t sb = (uint32_t)__cvta_generic_to_shared(smem);

    const int tid  = threadIdx.x;
    const int warp = tid >> 5;
    const int lane = tid & 31;
    const int g    = lane >> 2;
    const int tg   = lane & 3;
    const int wm   = warp >> 2;   // 0..3 (M)
    const int wn   = warp & 3;    // 0..3 (N)

    const int bm = blockIdx.y * 128;
    const int bn = blockIdx.x * 256;

    const int T = K / BK;

    // stage issue: A 512 chunks (1/thread), B 1024 chunks (2/thread); 16B each
    auto issue = [&](int s) {
        const uint32_t dst = sb + (s & (NST - 1)) * STG;
        {
            const int r = tid >> 2, c = tid & 3;
            cp16(dst + r * 64 + ((c ^ ((r >> 1) & 3)) << 4),
                 (const char*)A + (((long)(bm + r) * K + s * BK + c * 8) << 1));
        }
        #pragma unroll
        for (int i = 0; i < 2; i++) {
            const int id = tid + i * 512;
            const int r = id >> 2, c = id & 3;
            cp16(dst + ASTG + r * 64 + ((c ^ ((r >> 1) & 3)) << 4),
                 (const char*)Bt + (((long)(bn + r) * K + s * BK + c * 8) << 1));
        }
    };

    #pragma unroll
    for (int s = 0; s < NST - 1; s++) { issue(s); cp_commit(); }

    float acc[2][8][4] = {};

    for (int t = 0; t < T; t++) {
        asm volatile("cp.async.wait_group 2;" ::: "memory");
        __syncthreads();
        if (t + NST - 1 < T) issue(t + NST - 1);
        cp_commit();

        const uint32_t sA = sb + (t & (NST - 1)) * STG;
        const uint32_t sB = sA + ASTG;

        #pragma unroll
        for (int ks = 0; ks < 2; ks++) {       // two k16 steps
            uint32_t af[2][4];
            #pragma unroll
            for (int mi = 0; mi < 2; mi++) {
                const int row = wm * 32 + mi * 16 + (lane & 7) + ((lane >> 3) & 1) * 8;
                const int ch  = 2 * ks + (lane >> 4);
                ldsm4(af[mi], sA + row * 64 + ((ch ^ ((row >> 1) & 3)) << 4));
            }
            uint32_t bf[4][4];
            #pragma unroll
            for (int n2 = 0; n2 < 4; n2++) {
                const int row = wn * 64 + n2 * 16 + (lane & 7) + ((lane >> 3) & 1) * 8;
                const int ch  = 2 * ks + (lane >> 4);
                ldsm4(bf[n2], sB + row * 64 + ((ch ^ ((row >> 1) & 3)) << 4));
            }
            #pragma unroll
            for (int ni = 0; ni < 8; ni++) {
                const uint32_t b0 = bf[ni >> 1][ni & 1];
                const uint32_t b1 = bf[ni >> 1][2 + (ni & 1)];
                #pragma unroll
                for (int mi = 0; mi < 2; mi++)
                    mma_f16(acc[mi][ni], af[mi], b0, b1);
            }
        }
        // next iteration's wait+sync guards buffer reuse
    }

    // epilogue
    #pragma unroll
    for (int mi = 0; mi < 2; mi++) {
        const int r0 = bm + wm * 32 + mi * 16 + g;
        #pragma unroll
        for (int ni = 0; ni < 8; ni++) {
            const int cn = bn + wn * 64 + ni * 8 + 2 * tg;
            const float bz0 = bias[cn], bz1 = bias[cn + 1];
            float v00 = acc[mi][ni][0] + bz0;
            float v01 = acc[mi][ni][1] + bz1;
            float v10 = acc[mi][ni][2] + bz0;
            float v11 = acc[mi][ni][3] + bz1;
            const long o0 = (long)r0 * N + cn;
            const long o1 = (long)(r0 + 8) * N + cn;
            if (EPI == 1) {
                v00 += R[o0]; v01 += R[o0 + 1];
                v10 += R[o1]; v11 += R[o1 + 1];
                float* C = (float*)Cout;
                *(float2*)&C[o0] = make_float2(v00, v01);
                *(float2*)&C[o1] = make_float2(v10, v11);
            } else {
                if (EPI == 2) {
                    v00 = 0.5f * v00 * (1.f + erff(v00 * 0.70710678118654752f));
                    v01 = 0.5f * v01 * (1.f + erff(v01 * 0.70710678118654752f));
                    v10 = 0.5f * v10 * (1.f + erff(v10 * 0.70710678118654752f));
                    v11 = 0.5f * v11 * (1.f + erff(v11 * 0.70710678118654752f));
                }
                __half* C = (__half*)Cout;
                *(__half2*)&C[o0] = __floats2half2_rn(v00, v01);
                *(__half2*)&C[o1] = __floats2half2_rn(v10, v11);
            }
        }
    }
}

// ---------------- Sliding-window attention (fp16 IO, fp32 math) -----------
__global__ __launch_bounds__(128)
void attn_kernel(const __half* __restrict__ qkv, __half* __restrict__ out)
{
    const int qt = blockIdx.x, h = blockIdx.y, b = blockIdx.z;
    const int qi = qt * 128 + threadIdx.x;

    __shared__ float Kt[64][64];
    __shared__ float Vt[64][64];

    float q[DD];
    {
        const uint4* qp4 = (const uint4*)(qkv + ((long)(b * SS + qi)) * C3 + h * DD);
        #pragma unroll
        for (int i = 0; i < 8; i++) {
            uint4 u = qp4[i];
            const __half2* hp = (const __half2*)&u;
            #pragma unroll
            for (int j = 0; j < 4; j++) {
                float2 f = __half22float2(hp[j]);
                q[i * 8 + j * 2 + 0] = f.x * 0.125f;
                q[i * 8 + j * 2 + 1] = f.y * 0.125f;
            }
        }
    }

    float acc[DD] = {};
    float m = -1e30f, l = 0.f;

    const int kstart = qt * 128 - WW;
    const int r  = threadIdx.x >> 1;
    const int cb = (threadIdx.x & 1) * 32;

    for (int t = 0; t < 10; t++) {
        const int ks = kstart + t * 64;
        const int j = ks + r;
        if (j >= 0 && j < SS) {
            const uint4* kp4 = (const uint4*)(qkv + ((long)(b * SS + j)) * C3 + EE  + h * DD + cb);
            const uint4* vp4 = (const uint4*)(qkv + ((long)(b * SS + j)) * C3 + 2*EE + h * DD + cb);
            #pragma unroll
            for (int i = 0; i < 4; i++) {
                uint4 ku = kp4[i], vu = vp4[i];
                const __half2* khp = (const __half2*)&ku;
                const __half2* vhp = (const __half2*)&vu;
                #pragma unroll
                for (int jj = 0; jj < 4; jj++) {
                    float2 kf = __half22float2(khp[jj]);
                    float2 vf = __half22float2(vhp[jj]);
                    Kt[r][cb + i * 8 + jj * 2 + 0] = kf.x;
                    Kt[r][cb + i * 8 + jj * 2 + 1] = kf.y;
                    Vt[r][cb + i * 8 + jj * 2 + 0] = vf.x;
                    Vt[r][cb + i * 8 + jj * 2 + 1] = vf.y;
                }
            }
        } else {
            #pragma unroll
            for (int c = 0; c < 32; c += 4) {
                *(float4*)&Kt[r][cb + c] = make_float4(0.f, 0.f, 0.f, 0.f);
                *(float4*)&Vt[r][cb + c] = make_float4(0.f, 0.f, 0.f, 0.f);
            }
        }
        __syncthreads();

        for (int jj = 0; jj < 64; jj++) {
            const int j2 = ks + jj;
            const bool valid = (j2 >= 0) & (j2 < SS) &
                               (j2 >= qi - WW) & (j2 <= qi + WW);
            if (valid) {
                float s = 0.f;
                #pragma unroll
                for (int d = 0; d < DD; d++) s += q[d] * Kt[jj][d];
                if (s > m) {
                    const float c = __expf(m - s);
                    l *= c;
                    #pragma unroll
                    for (int d = 0; d < DD; d++) acc[d] *= c;
                    m = s;
                }
                const float p = __expf(s - m);
                l += p;
                #pragma unroll
                for (int d = 0; d < DD; d++) acc[d] += p * Vt[jj][d];
            }
        }
        __syncthreads();
    }

    const float inv = 1.f / l;
    __half* op = out + ((long)(b * SS + qi)) * EE + h * DD;
    #pragma unroll
    for (int d = 0; d < DD; d += 2)
        *(__half2*)&op[d] = __floats2half2_rn(acc[d] * inv, acc[d + 1] * inv);
}

// ---------------- launch ----------------
extern "C" void kernel_launch(void* const* d_in, const int* in_sizes, int n_in,
                              void* d_out, int out_size)
{
    const float* x        = (const float*)d_in[0];
    const float* ln1_g    = (const float*)d_in[1];
    const float* ln1_b    = (const float*)d_in[2];
    const float* c_attn_w = (const float*)d_in[3];
    const float* c_attn_b = (const float*)d_in[4];
    const float* c_proj_w = (const float*)d_in[5];
    const float* c_proj_b = (const float*)d_in[6];
    const float* ln2_g    = (const float*)d_in[7];
    const float* ln2_b    = (const float*)d_in[8];
    const float* fc_w     = (const float*)d_in[9];
    const float* fc_b     = (const float*)d_in[10];
    const float* proj2_w  = (const float*)d_in[11];
    const float* proj2_b  = (const float*)d_in[12];
    float* out = (float*)d_out;

    __half *h, *qkv, *attn, *ff;
    float *x1;
    __half *wT_attn, *wT_proj, *wT_fc, *wT_proj2;
    cudaGetSymbolAddress((void**)&h,    g_buf_h);
    cudaGetSymbolAddress((void**)&qkv,  g_buf_qkv);
    cudaGetSymbolAddress((void**)&attn, g_buf_attn);
    cudaGetSymbolAddress((void**)&x1,   g_buf_x1);
    cudaGetSymbolAddress((void**)&ff,   g_buf_ff);
    cudaGetSymbolAddress((void**)&wT_attn,  g_wT_attn);
    cudaGetSymbolAddress((void**)&wT_proj,  g_wT_proj);
    cudaGetSymbolAddress((void**)&wT_fc,    g_wT_fc);
    cudaGetSymbolAddress((void**)&wT_proj2, g_wT_proj2);

    cudaFuncSetAttribute(hgemm<0>, cudaFuncAttributeMaxDynamicSharedMemorySize, HG_SMEM);
    cudaFuncSetAttribute(hgemm<1>, cudaFuncAttributeMaxDynamicSharedMemorySize, HG_SMEM);
    cudaFuncSetAttribute(hgemm<2>, cudaFuncAttributeMaxDynamicSharedMemorySize, HG_SMEM);

    dim3 tb(32, 8);
    transpose_kernel<<<dim3(C3 / 32, EE / 32), tb>>>(c_attn_w, wT_attn, EE, C3);
    transpose_kernel<<<dim3(EE / 32, EE / 32), tb>>>(c_proj_w, wT_proj, EE, EE);
    transpose_kernel<<<dim3(E4 / 32, EE / 32), tb>>>(fc_w,     wT_fc,   EE, E4);
    transpose_kernel<<<dim3(EE / 32, E4 / 32), tb>>>(proj2_w,  wT_proj2, E4, EE);

    ln_kernel<<<ROWS, 256>>>(x, ln1_g, ln1_b, h);
    hgemm<0><<<dim3(C3 / 256, ROWS / 128), 512, HG_SMEM>>>(
        h, wT_attn, c_attn_b, nullptr, qkv, ROWS, C3, EE);
    attn_kernel<<<dim3(SS / 128, HH, BB), 128>>>(qkv, attn);
    hgemm<1><<<dim3(EE / 256, ROWS / 128), 512, HG_SMEM>>>(
        attn, wT_proj, c_proj_b, x, x1, ROWS, EE, EE);
    ln_kernel<<<ROWS, 256>>>(x1, ln2_g, ln2_b, h);
    hgemm<2><<<dim3(E4 / 256, ROWS / 128), 512, HG_SMEM>>>(
        h, wT_fc, fc_b, nullptr, ff, ROWS, E4, EE);
    hgemm<1><<<dim3(EE / 256, ROWS / 128), 512, HG_SMEM>>>(
        ff, wT_proj2, proj2_b, x1, out, ROWS, EE, E4);
}

// round 12
// speedup vs baseline: 5.8163x; 2.0041x over previous
#include <cuda_runtime.h>
#include <cuda_fp16.h>
#include <math.h>
#include <stdint.h>

// Problem constants
#define BB 2
#define SS 4096
#define EE 768
#define HH 12
#define DD 64
#define WW 256
#define ROWS (BB*SS)          // 8192
#define C3 (3*EE)             // 2304
#define E4 (4*EE)             // 3072

// ---------------- scratch (static device allocations) ----------------
__device__ __half g_buf_h   [ROWS * EE];   // LN outputs (GEMM A input)
__device__ __half g_buf_qkv [ROWS * C3];
__device__ __half g_buf_attn[ROWS * EE];
__device__ float  g_buf_x1  [ROWS * EE];   // residual stream stays fp32
__device__ __half g_buf_ff  [ROWS * E4];
// transposed fp16 weights [N,K] row-major (K contiguous)
__device__ __half g_wT_attn [C3 * EE];
__device__ __half g_wT_proj [EE * EE];
__device__ __half g_wT_fc   [E4 * EE];
__device__ __half g_wT_proj2[EE * E4];

// ---------------- asm helpers ----------------
__device__ __forceinline__ void mma_f16(float c[4], const uint32_t a[4],
                                        uint32_t b0, uint32_t b1) {
    asm volatile(
        "mma.sync.aligned.m16n8k16.row.col.f32.f16.f16.f32 "
        "{%0,%1,%2,%3}, {%4,%5,%6,%7}, {%8,%9}, {%0,%1,%2,%3};"
        : "+f"(c[0]), "+f"(c[1]), "+f"(c[2]), "+f"(c[3])
        : "r"(a[0]), "r"(a[1]), "r"(a[2]), "r"(a[3]), "r"(b0), "r"(b1));
}

__device__ __forceinline__ void ldsm4(uint32_t r[4], uint32_t addr) {
    asm volatile("ldmatrix.sync.aligned.m8n8.x4.shared.b16 {%0,%1,%2,%3}, [%4];"
                 : "=r"(r[0]), "=r"(r[1]), "=r"(r[2]), "=r"(r[3]) : "r"(addr));
}

__device__ __forceinline__ void ldsm4t(uint32_t r[4], uint32_t addr) {
    asm volatile("ldmatrix.sync.aligned.m8n8.x4.trans.shared.b16 {%0,%1,%2,%3}, [%4];"
                 : "=r"(r[0]), "=r"(r[1]), "=r"(r[2]), "=r"(r[3]) : "r"(addr));
}

__device__ __forceinline__ void cp16(uint32_t saddr, const void* gptr) {
    asm volatile("cp.async.cg.shared.global [%0], [%1], 16;\n"
                 :: "r"(saddr), "l"(gptr));
}
__device__ __forceinline__ void cp_commit() {
    asm volatile("cp.async.commit_group;\n" ::: "memory");
}

__device__ __forceinline__ float ex2(float x) {
    float y;
    asm("ex2.approx.ftz.f32 %0, %1;" : "=f"(y) : "f"(x));
    return y;
}

// pack two floats to one fp16x2 register (full 32 bits)
__device__ __forceinline__ uint32_t pack_h2(float a, float b) {
    __half2 t = __floats2half2_rn(a, b);
    return *reinterpret_cast<uint32_t*>(&t);
}

// ---------------- LayerNorm (fp32 in, fp16 out) ----------------
__global__ __launch_bounds__(256)
void ln_kernel(const float* __restrict__ x, const float* __restrict__ g,
               const float* __restrict__ b, __half* __restrict__ out)
{
    const int row = blockIdx.x;
    const int tid = threadIdx.x;
    const float* xr = x + (long)row * EE;
    float v0 = xr[tid], v1 = xr[tid + 256], v2 = xr[tid + 512];
    float s  = v0 + v1 + v2;
    float sq = v0*v0 + v1*v1 + v2*v2;

    __shared__ float sh_s[8], sh_q[8];
    #pragma unroll
    for (int o = 16; o > 0; o >>= 1) {
        s  += __shfl_xor_sync(0xffffffffu, s,  o);
        sq += __shfl_xor_sync(0xffffffffu, sq, o);
    }
    const int wid = tid >> 5, lane = tid & 31;
    if (lane == 0) { sh_s[wid] = s; sh_q[wid] = sq; }
    __syncthreads();
    if (wid == 0) {
        s  = (lane < 8) ? sh_s[lane] : 0.f;
        sq = (lane < 8) ? sh_q[lane] : 0.f;
        #pragma unroll
        for (int o = 4; o > 0; o >>= 1) {
            s  += __shfl_xor_sync(0xffffffffu, s,  o);
            sq += __shfl_xor_sync(0xffffffffu, sq, o);
        }
        if (lane == 0) { sh_s[0] = s; sh_q[0] = sq; }
    }
    __syncthreads();
    const float mean = sh_s[0] * (1.f / EE);
    const float var  = sh_q[0] * (1.f / EE) - mean * mean;
    const float inv  = rsqrtf(var + 1e-5f);

    __half* orow = out + (long)row * EE;
    orow[tid      ] = __float2half_rn((v0 - mean) * inv * g[tid      ] + b[tid      ]);
    orow[tid + 256] = __float2half_rn((v1 - mean) * inv * g[tid + 256] + b[tid + 256]);
    orow[tid + 512] = __float2half_rn((v2 - mean) * inv * g[tid + 512] + b[tid + 512]);
}

// ---------------- weight transpose+convert: fp32 [K,N] -> fp16 [N,K] ------
__global__ __launch_bounds__(256)
void transpose_kernel(const float* __restrict__ in, __half* __restrict__ out,
                      int K, int N)
{
    __shared__ float tile[32][33];
    const int bx = blockIdx.x * 32;   // N
    const int by = blockIdx.y * 32;   // K
    const int tx = threadIdx.x, ty = threadIdx.y;
    #pragma unroll
    for (int i = ty; i < 32; i += 8)
        tile[i][tx] = in[(long)(by + i) * N + bx + tx];
    __syncthreads();
    #pragma unroll
    for (int i = ty; i < 32; i += 8)
        out[(long)(bx + i) * K + by + tx] = __float2half_rn(tile[tx][i]);
}

// ---------------- fp16 HMMA GEMM ----------------------
#define BK 32
#define ASTG (128 * 64)
#define BSTG (256 * 64)
#define STG  (ASTG + BSTG)
#define NST  4
#define HG_SMEM (NST * STG)

template<int EPI>
__global__ __launch_bounds__(512, 1)
void hgemm(const __half* __restrict__ A, const __half* __restrict__ Bt,
           const float* __restrict__ bias, const float* __restrict__ R,
           void* __restrict__ Cout, int M, int N, int K)
{
    extern __shared__ char smem[];
    const uint32_t sb = (uint32_t)__cvta_generic_to_shared(smem);

    const int tid  = threadIdx.x;
    const int warp = tid >> 5;
    const int lane = tid & 31;
    const int g    = lane >> 2;
    const int tg   = lane & 3;
    const int wm   = warp >> 2;
    const int wn   = warp & 3;

    const int bm = blockIdx.y * 128;
    const int bn = blockIdx.x * 256;

    const int T = K / BK;

    auto issue = [&](int s) {
        const uint32_t dst = sb + (s & (NST - 1)) * STG;
        {
            const int r = tid >> 2, c = tid & 3;
            cp16(dst + r * 64 + ((c ^ ((r >> 1) & 3)) << 4),
                 (const char*)A + (((long)(bm + r) * K + s * BK + c * 8) << 1));
        }
        #pragma unroll
        for (int i = 0; i < 2; i++) {
            const int id = tid + i * 512;
            const int r = id >> 2, c = id & 3;
            cp16(dst + ASTG + r * 64 + ((c ^ ((r >> 1) & 3)) << 4),
                 (const char*)Bt + (((long)(bn + r) * K + s * BK + c * 8) << 1));
        }
    };

    #pragma unroll
    for (int s = 0; s < NST - 1; s++) { issue(s); cp_commit(); }

    float acc[2][8][4] = {};

    for (int t = 0; t < T; t++) {
        asm volatile("cp.async.wait_group 2;" ::: "memory");
        __syncthreads();
        if (t + NST - 1 < T) issue(t + NST - 1);
        cp_commit();

        const uint32_t sA = sb + (t & (NST - 1)) * STG;
        const uint32_t sB = sA + ASTG;

        #pragma unroll
        for (int ks = 0; ks < 2; ks++) {
            uint32_t af[2][4];
            #pragma unroll
            for (int mi = 0; mi < 2; mi++) {
                const int row = wm * 32 + mi * 16 + (lane & 7) + ((lane >> 3) & 1) * 8;
                const int ch  = 2 * ks + (lane >> 4);
                ldsm4(af[mi], sA + row * 64 + ((ch ^ ((row >> 1) & 3)) << 4));
            }
            uint32_t bf[4][4];
            #pragma unroll
            for (int n2 = 0; n2 < 4; n2++) {
                const int row = wn * 64 + n2 * 16 + (lane & 7) + ((lane >> 3) & 1) * 8;
                const int ch  = 2 * ks + (lane >> 4);
                ldsm4(bf[n2], sB + row * 64 + ((ch ^ ((row >> 1) & 3)) << 4));
            }
            #pragma unroll
            for (int ni = 0; ni < 8; ni++) {
                const uint32_t b0 = bf[ni >> 1][ni & 1];
                const uint32_t b1 = bf[ni >> 1][2 + (ni & 1)];
                #pragma unroll
                for (int mi = 0; mi < 2; mi++)
                    mma_f16(acc[mi][ni], af[mi], b0, b1);
            }
        }
    }

    #pragma unroll
    for (int mi = 0; mi < 2; mi++) {
        const int r0 = bm + wm * 32 + mi * 16 + g;
        #pragma unroll
        for (int ni = 0; ni < 8; ni++) {
            const int cn = bn + wn * 64 + ni * 8 + 2 * tg;
            const float bz0 = bias[cn], bz1 = bias[cn + 1];
            float v00 = acc[mi][ni][0] + bz0;
            float v01 = acc[mi][ni][1] + bz1;
            float v10 = acc[mi][ni][2] + bz0;
            float v11 = acc[mi][ni][3] + bz1;
            const long o0 = (long)r0 * N + cn;
            const long o1 = (long)(r0 + 8) * N + cn;
            if (EPI == 1) {
                v00 += R[o0]; v01 += R[o0 + 1];
                v10 += R[o1]; v11 += R[o1 + 1];
                float* C = (float*)Cout;
                *(float2*)&C[o0] = make_float2(v00, v01);
                *(float2*)&C[o1] = make_float2(v10, v11);
            } else {
                if (EPI == 2) {
                    v00 = 0.5f * v00 * (1.f + erff(v00 * 0.70710678118654752f));
                    v01 = 0.5f * v01 * (1.f + erff(v01 * 0.70710678118654752f));
                    v10 = 0.5f * v10 * (1.f + erff(v10 * 0.70710678118654752f));
                    v11 = 0.5f * v11 * (1.f + erff(v11 * 0.70710678118654752f));
                }
                __half* C = (__half*)Cout;
                *(__half2*)&C[o0] = __floats2half2_rn(v00, v01);
                *(__half2*)&C[o1] = __floats2half2_rn(v10, v11);
            }
        }
    }
}

// ---------------- Flash attention with fp16 HMMA ---------------------------
#define ASC 0.18033688011112042f   // 0.125 * log2(e)

__device__ __forceinline__ uint32_t arow_off(int r, int c) {
    return (uint32_t)(r * 128 + ((c ^ (r & 7)) << 4));
}

__global__ __launch_bounds__(128)
void attn_kernel(const __half* __restrict__ qkv, __half* __restrict__ out)
{
    __shared__ __half sQ[64 * 64];
    __shared__ __half sK[2][64 * 64];
    __shared__ __half sV[2][64 * 64];

    const int qt = blockIdx.x, h = blockIdx.y, b = blockIdx.z;
    const int qb = qt * 64;
    const int tid = threadIdx.x;
    const int w = tid >> 5, lane = tid & 31;
    const int g = lane >> 2, tg = lane & 3;

    const uint32_t sQb = (uint32_t)__cvta_generic_to_shared(sQ);
    const uint32_t sKb[2] = { (uint32_t)__cvta_generic_to_shared(sK[0]),
                              (uint32_t)__cvta_generic_to_shared(sK[1]) };
    const uint32_t sVb[2] = { (uint32_t)__cvta_generic_to_shared(sV[0]),
                              (uint32_t)__cvta_generic_to_shared(sV[1]) };

    const long rowbase = (long)(b * SS);
    const __half* Qg = qkv + h * DD;
    const __half* Kg = qkv + EE + h * DD;
    const __half* Vg = qkv + 2 * EE + h * DD;

    const int tstart = (qb >= 193) ? 0 : (193 - qb + 63) / 64;
    const int tend   = min(8, (4351 - qb) / 64);

    #pragma unroll
    for (int i = 0; i < 4; i++) {
        const int id = tid + i * 128, r = id >> 3, c = id & 7;
        cp16(sQb + arow_off(r, c), (const char*)(Qg + (rowbase + qb + r) * C3) + c * 16);
    }
    auto issue = [&](int t, int buf) {
        const int kbase = qb - 256 + 64 * t;
        #pragma unroll
        for (int i = 0; i < 4; i++) {
            const int id = tid + i * 128, r = id >> 3, c = id & 7;
            int j = kbase + r; j = j < 0 ? 0 : (j >= SS ? SS - 1 : j);
            cp16(sKb[buf] + arow_off(r, c), (const char*)(Kg + (rowbase + j) * C3) + c * 16);
            cp16(sVb[buf] + arow_off(r, c), (const char*)(Vg + (rowbase + j) * C3) + c * 16);
        }
    };

    issue(tstart, 0);
    cp_commit();

    uint32_t aq[4][4];
    float acc_o[8][4] = {};
    float m0 = -1e30f, m1 = -1e30f, l0 = 0.f, l1 = 0.f;
    const int i0 = qb + w * 16 + g;
    const int i1 = i0 + 8;

    for (int t = tstart; t <= tend; t++) {
        const int buf = (t - tstart) & 1;
        if (t < tend) { issue(t + 1, buf ^ 1); cp_commit(); }
        if (t < tend) asm volatile("cp.async.wait_group 1;" ::: "memory");
        else          asm volatile("cp.async.wait_group 0;" ::: "memory");
        __syncthreads();

        if (t == tstart) {
            #pragma unroll
            for (int ks = 0; ks < 4; ks++) {
                const int row = w * 16 + (lane & 7) + ((lane >> 3) & 1) * 8;
                const int ch  = 2 * ks + (lane >> 4);
                ldsm4(aq[ks], sQb + arow_off(row, ch));
            }
        }

        const int kbase = qb - 256 + 64 * t;

        // ---- scores S = Q K^T ----
        float s[8][4] = {};
        #pragma unroll
        for (int ks = 0; ks < 4; ks++) {
            uint32_t bk[4][4];
            #pragma unroll
            for (int n2 = 0; n2 < 4; n2++) {
                const int row = n2 * 16 + (lane & 7) + ((lane >> 3) & 1) * 8;
                const int ch  = 2 * ks + (lane >> 4);
                ldsm4(bk[n2], sKb[buf] + arow_off(row, ch));
            }
            #pragma unroll
            for (int ni = 0; ni < 8; ni++)
                mma_f16(s[ni], aq[ks], bk[ni >> 1][ni & 1], bk[ni >> 1][2 + (ni & 1)]);
        }

        // ---- mask ----
        const bool masked = (t == 0) | (t == 8) | (kbase < 0) | (kbase + 63 >= SS);
        if (masked) {
            #pragma unroll
            for (int ni = 0; ni < 8; ni++) {
                #pragma unroll
                for (int c = 0; c < 2; c++) {
                    const int j = kbase + ni * 8 + 2 * tg + c;
                    const bool inseq = (j >= 0) & (j < SS);
                    if (!(inseq & (j >= i0 - WW) & (j <= i0 + WW))) s[ni][c]     = -1e30f;
                    if (!(inseq & (j >= i1 - WW) & (j <= i1 + WW))) s[ni][c + 2] = -1e30f;
                }
            }
        }

        // ---- online softmax ----
        float mx0 = s[0][0], mx1 = s[0][2];
        #pragma unroll
        for (int ni = 0; ni < 8; ni++) {
            mx0 = fmaxf(mx0, fmaxf(s[ni][0], s[ni][1]));
            mx1 = fmaxf(mx1, fmaxf(s[ni][2], s[ni][3]));
        }
        mx0 = fmaxf(mx0, __shfl_xor_sync(0xffffffffu, mx0, 1));
        mx0 = fmaxf(mx0, __shfl_xor_sync(0xffffffffu, mx0, 2));
        mx1 = fmaxf(mx1, __shfl_xor_sync(0xffffffffu, mx1, 1));
        mx1 = fmaxf(mx1, __shfl_xor_sync(0xffffffffu, mx1, 2));
        const float mn0 = fmaxf(m0, mx0), mn1 = fmaxf(m1, mx1);
        const float f0 = ex2((m0 - mn0) * ASC), f1 = ex2((m1 - mn1) * ASC);
        m0 = mn0; m1 = mn1;

        float ps0 = 0.f, ps1 = 0.f;
        #pragma unroll
        for (int ni = 0; ni < 8; ni++) {
            s[ni][0] = ex2((s[ni][0] - mn0) * ASC);
            s[ni][1] = ex2((s[ni][1] - mn0) * ASC);
            s[ni][2] = ex2((s[ni][2] - mn1) * ASC);
            s[ni][3] = ex2((s[ni][3] - mn1) * ASC);
            ps0 += s[ni][0] + s[ni][1];
            ps1 += s[ni][2] + s[ni][3];
        }
        // l0/l1 remain PER-THREAD partials (keys == {2tg,2tg+1} mod 8);
        // f factors are quad-uniform, so reduce across the quad once at the end.
        l0 = l0 * f0 + ps0;
        l1 = l1 * f1 + ps1;
        #pragma unroll
        for (int nd = 0; nd < 8; nd++) {
            acc_o[nd][0] *= f0; acc_o[nd][1] *= f0;
            acc_o[nd][2] *= f1; acc_o[nd][3] *= f1;
        }

        // ---- PV: O += P V ----
        #pragma unroll
        for (int kk = 0; kk < 4; kk++) {
            uint32_t pa[4];
            pa[0] = pack_h2(s[2*kk][0],   s[2*kk][1]);
            pa[1] = pack_h2(s[2*kk][2],   s[2*kk][3]);
            pa[2] = pack_h2(s[2*kk+1][0], s[2*kk+1][1]);
            pa[3] = pack_h2(s[2*kk+1][2], s[2*kk+1][3]);
            #pragma unroll
            for (int d2 = 0; d2 < 4; d2++) {
                uint32_t bv[4];
                const int row = kk * 16 + (lane & 7) + ((lane >> 3) & 1) * 8;
                const int ch  = 2 * d2 + (lane >> 4);
                ldsm4t(bv, sVb[buf] + arow_off(row, ch));
                mma_f16(acc_o[2 * d2],     pa, bv[0], bv[1]);
                mma_f16(acc_o[2 * d2 + 1], pa, bv[2], bv[3]);
            }
        }
        __syncthreads();
    }

    // ---- FIX: reduce the softmax denominator across the quad ----
    l0 += __shfl_xor_sync(0xffffffffu, l0, 1);
    l0 += __shfl_xor_sync(0xffffffffu, l0, 2);
    l1 += __shfl_xor_sync(0xffffffffu, l1, 1);
    l1 += __shfl_xor_sync(0xffffffffu, l1, 2);

    // ---- write out ----
    const float r0 = 1.f / l0, r1 = 1.f / l1;
    __half* o0 = out + (rowbase + i0) * EE + h * DD + 2 * tg;
    __half* o1 = out + (rowbase + i1) * EE + h * DD + 2 * tg;
    #pragma unroll
    for (int nd = 0; nd < 8; nd++) {
        *(__half2*)(o0 + nd * 8) = __floats2half2_rn(acc_o[nd][0] * r0, acc_o[nd][1] * r0);
        *(__half2*)(o1 + nd * 8) = __floats2half2_rn(acc_o[nd][2] * r1, acc_o[nd][3] * r1);
    }
}

// ---------------- launch ----------------
extern "C" void kernel_launch(void* const* d_in, const int* in_sizes, int n_in,
                              void* d_out, int out_size)
{
    const float* x        = (const float*)d_in[0];
    const float* ln1_g    = (const float*)d_in[1];
    const float* ln1_b    = (const float*)d_in[2];
    const float* c_attn_w = (const float*)d_in[3];
    const float* c_attn_b = (const float*)d_in[4];
    const float* c_proj_w = (const float*)d_in[5];
    const float* c_proj_b = (const float*)d_in[6];
    const float* ln2_g    = (const float*)d_in[7];
    const float* ln2_b    = (const float*)d_in[8];
    const float* fc_w     = (const float*)d_in[9];
    const float* fc_b     = (const float*)d_in[10];
    const float* proj2_w  = (const float*)d_in[11];
    const float* proj2_b  = (const float*)d_in[12];
    float* out = (float*)d_out;

    __half *h, *qkv, *attn, *ff;
    float *x1;
    __half *wT_attn, *wT_proj, *wT_fc, *wT_proj2;
    cudaGetSymbolAddress((void**)&h,    g_buf_h);
    cudaGetSymbolAddress((void**)&qkv,  g_buf_qkv);
    cudaGetSymbolAddress((void**)&attn, g_buf_attn);
    cudaGetSymbolAddress((void**)&x1,   g_buf_x1);
    cudaGetSymbolAddress((void**)&ff,   g_buf_ff);
    cudaGetSymbolAddress((void**)&wT_attn,  g_wT_attn);
    cudaGetSymbolAddress((void**)&wT_proj,  g_wT_proj);
    cudaGetSymbolAddress((void**)&wT_fc,    g_wT_fc);
    cudaGetSymbolAddress((void**)&wT_proj2, g_wT_proj2);

    cudaFuncSetAttribute(hgemm<0>, cudaFuncAttributeMaxDynamicSharedMemorySize, HG_SMEM);
    cudaFuncSetAttribute(hgemm<1>, cudaFuncAttributeMaxDynamicSharedMemorySize, HG_SMEM);
    cudaFuncSetAttribute(hgemm<2>, cudaFuncAttributeMaxDynamicSharedMemorySize, HG_SMEM);

    dim3 tb(32, 8);
    transpose_kernel<<<dim3(C3 / 32, EE / 32), tb>>>(c_attn_w, wT_attn, EE, C3);
    transpose_kernel<<<dim3(EE / 32, EE / 32), tb>>>(c_proj_w, wT_proj, EE, EE);
    transpose_kernel<<<dim3(E4 / 32, EE / 32), tb>>>(fc_w,     wT_fc,   EE, E4);
    transpose_kernel<<<dim3(EE / 32, E4 / 32), tb>>>(proj2_w,  wT_proj2, E4, EE);

    ln_kernel<<<ROWS, 256>>>(x, ln1_g, ln1_b, h);
    hgemm<0><<<dim3(C3 / 256, ROWS / 128), 512, HG_SMEM>>>(
        h, wT_attn, c_attn_b, nullptr, qkv, ROWS, C3, EE);
    attn_kernel<<<dim3(SS / 64, HH, BB), 128>>>(qkv, attn);
    hgemm<1><<<dim3(EE / 256, ROWS / 128), 512, HG_SMEM>>>(
        attn, wT_proj, c_proj_b, x, x1, ROWS, EE, EE);
    ln_kernel<<<ROWS, 256>>>(x1, ln2_g, ln2_b, h);
    hgemm<2><<<dim3(E4 / 256, ROWS / 128), 512, HG_SMEM>>>(
        h, wT_fc, fc_b, nullptr, ff, ROWS, E4, EE);
    hgemm<1><<<dim3(EE / 256, ROWS / 128), 512, HG_SMEM>>>(
        ff, wT_proj2, proj2_b, x1, out, ROWS, EE, E4);
}

// round 13
// speedup vs baseline: 7.4212x; 1.2759x over previous
#include <cuda_runtime.h>
#include <cuda_fp16.h>
#include <math.h>
#include <stdint.h>

// Problem constants
#define BB 2
#define SS 4096
#define EE 768
#define HH 12
#define DD 64
#define WW 256
#define ROWS (BB*SS)          // 8192
#define C3 (3*EE)             // 2304
#define E4 (4*EE)             // 3072

// ---------------- scratch (static device allocations) ----------------
__device__ __half g_buf_h   [ROWS * EE];   // LN outputs (GEMM A input)
__device__ __half g_buf_qkv [ROWS * C3];
__device__ __half g_buf_attn[ROWS * EE];
__device__ float  g_buf_x1  [ROWS * EE];   // residual stream stays fp32
__device__ __half g_buf_ff  [ROWS * E4];
// transposed fp16 weights [N,K] row-major (K contiguous)
__device__ __half g_wT_attn [C3 * EE];
__device__ __half g_wT_proj [EE * EE];
__device__ __half g_wT_fc   [E4 * EE];
__device__ __half g_wT_proj2[EE * E4];

// ---------------- asm helpers ----------------
__device__ __forceinline__ void mma_f16(float c[4], const uint32_t a[4],
                                        uint32_t b0, uint32_t b1) {
    asm volatile(
        "mma.sync.aligned.m16n8k16.row.col.f32.f16.f16.f32 "
        "{%0,%1,%2,%3}, {%4,%5,%6,%7}, {%8,%9}, {%0,%1,%2,%3};"
        : "+f"(c[0]), "+f"(c[1]), "+f"(c[2]), "+f"(c[3])
        : "r"(a[0]), "r"(a[1]), "r"(a[2]), "r"(a[3]), "r"(b0), "r"(b1));
}

__device__ __forceinline__ void ldsm4(uint32_t r[4], uint32_t addr) {
    asm volatile("ldmatrix.sync.aligned.m8n8.x4.shared.b16 {%0,%1,%2,%3}, [%4];"
                 : "=r"(r[0]), "=r"(r[1]), "=r"(r[2]), "=r"(r[3]) : "r"(addr));
}

__device__ __forceinline__ void ldsm4t(uint32_t r[4], uint32_t addr) {
    asm volatile("ldmatrix.sync.aligned.m8n8.x4.trans.shared.b16 {%0,%1,%2,%3}, [%4];"
                 : "=r"(r[0]), "=r"(r[1]), "=r"(r[2]), "=r"(r[3]) : "r"(addr));
}

__device__ __forceinline__ void cp16(uint32_t saddr, const void* gptr) {
    asm volatile("cp.async.cg.shared.global [%0], [%1], 16;\n"
                 :: "r"(saddr), "l"(gptr));
}
__device__ __forceinline__ void cp_commit() {
    asm volatile("cp.async.commit_group;\n" ::: "memory");
}

__device__ __forceinline__ float ex2(float x) {
    float y;
    asm("ex2.approx.ftz.f32 %0, %1;" : "=f"(y) : "f"(x));
    return y;
}

// pack two floats to one fp16x2 register (full 32 bits)
__device__ __forceinline__ uint32_t pack_h2(float a, float b) {
    __half2 t = __floats2half2_rn(a, b);
    return *reinterpret_cast<uint32_t*>(&t);
}

// shared 128B-row swizzle: row r (128 B), 16B chunk c: conflict-free ldmatrix
__device__ __forceinline__ uint32_t arow_off(int r, int c) {
    return (uint32_t)(r * 128 + ((c ^ (r & 7)) << 4));
}

// ---------------- LayerNorm (fp32 in, fp16 out) ----------------
__global__ __launch_bounds__(256)
void ln_kernel(const float* __restrict__ x, const float* __restrict__ g,
               const float* __restrict__ b, __half* __restrict__ out)
{
    const int row = blockIdx.x;
    const int tid = threadIdx.x;
    const float* xr = x + (long)row * EE;
    float v0 = xr[tid], v1 = xr[tid + 256], v2 = xr[tid + 512];
    float s  = v0 + v1 + v2;
    float sq = v0*v0 + v1*v1 + v2*v2;

    __shared__ float sh_s[8], sh_q[8];
    #pragma unroll
    for (int o = 16; o > 0; o >>= 1) {
        s  += __shfl_xor_sync(0xffffffffu, s,  o);
        sq += __shfl_xor_sync(0xffffffffu, sq, o);
    }
    const int wid = tid >> 5, lane = tid & 31;
    if (lane == 0) { sh_s[wid] = s; sh_q[wid] = sq; }
    __syncthreads();
    if (wid == 0) {
        s  = (lane < 8) ? sh_s[lane] : 0.f;
        sq = (lane < 8) ? sh_q[lane] : 0.f;
        #pragma unroll
        for (int o = 4; o > 0; o >>= 1) {
            s  += __shfl_xor_sync(0xffffffffu, s,  o);
            sq += __shfl_xor_sync(0xffffffffu, sq, o);
        }
        if (lane == 0) { sh_s[0] = s; sh_q[0] = sq; }
    }
    __syncthreads();
    const float mean = sh_s[0] * (1.f / EE);
    const float var  = sh_q[0] * (1.f / EE) - mean * mean;
    const float inv  = rsqrtf(var + 1e-5f);

    __half* orow = out + (long)row * EE;
    orow[tid      ] = __float2half_rn((v0 - mean) * inv * g[tid      ] + b[tid      ]);
    orow[tid + 256] = __float2half_rn((v1 - mean) * inv * g[tid + 256] + b[tid + 256]);
    orow[tid + 512] = __float2half_rn((v2 - mean) * inv * g[tid + 512] + b[tid + 512]);
}

// ---------------- weight transpose+convert: fp32 [K,N] -> fp16 [N,K] ------
__global__ __launch_bounds__(256)
void transpose_kernel(const float* __restrict__ in, __half* __restrict__ out,
                      int K, int N)
{
    __shared__ float tile[32][33];
    const int bx = blockIdx.x * 32;   // N
    const int by = blockIdx.y * 32;   // K
    const int tx = threadIdx.x, ty = threadIdx.y;
    #pragma unroll
    for (int i = ty; i < 32; i += 8)
        tile[i][tx] = in[(long)(by + i) * N + bx + tx];
    __syncthreads();
    #pragma unroll
    for (int i = ty; i < 32; i += 8)
        out[(long)(bx + i) * K + by + tx] = __float2half_rn(tile[tx][i]);
}

// ---------------- fp16 HMMA GEMM -----------------------------------------
// 128x128 tile, BK=64, 256 threads = 8 warps (4x2), warp tile 32x64.
// 3-stage cp.async, 128B-row swizzle, 2 CTAs/SM.
// EPI: 0 = +bias -> half   1 = +bias+res(fp32) -> float   2 = gelu -> half
#define GBK 64
#define GASTG (128 * 128)          // A stage: 128 rows x 128B = 16KB
#define GBSTG (128 * 128)          // B stage: 16KB
#define GSTG  (GASTG + GBSTG)      // 32KB
#define GNST  3
#define HG_SMEM (GNST * GSTG)      // 98304 B

template<int EPI>
__global__ __launch_bounds__(256, 2)
void hgemm(const __half* __restrict__ A, const __half* __restrict__ Bt,
           const float* __restrict__ bias, const float* __restrict__ R,
           void* __restrict__ Cout, int M, int N, int K)
{
    extern __shared__ char smem[];
    const uint32_t sb = (uint32_t)__cvta_generic_to_shared(smem);

    const int tid  = threadIdx.x;
    const int warp = tid >> 5;
    const int lane = tid & 31;
    const int g    = lane >> 2;
    const int tg   = lane & 3;
    const int wm   = warp >> 1;   // 0..3 (M)
    const int wn   = warp & 1;    // 0..1 (N)

    const int bm = blockIdx.y * 128;
    const int bn = blockIdx.x * 128;

    const int T = K / GBK;

    // per stage: A 1024 chunks of 16B, B 1024 chunks; 4 each per thread
    auto issue = [&](int s) {
        const uint32_t dst = sb + (s % GNST) * GSTG;
        #pragma unroll
        for (int i = 0; i < 4; i++) {
            const int id = tid + i * 256;
            const int r = id >> 3, c = id & 7;
            cp16(dst + arow_off(r, c),
                 (const char*)A + (((long)(bm + r) * K + s * GBK + c * 8) << 1));
        }
        #pragma unroll
        for (int i = 0; i < 4; i++) {
            const int id = tid + i * 256;
            const int r = id >> 3, c = id & 7;
            cp16(dst + GASTG + arow_off(r, c),
                 (const char*)Bt + (((long)(bn + r) * K + s * GBK + c * 8) << 1));
        }
    };

    issue(0); cp_commit();
    issue(1); cp_commit();

    float acc[2][8][4] = {};

    for (int t = 0; t < T; t++) {
        asm volatile("cp.async.wait_group 1;" ::: "memory");
        __syncthreads();
        if (t + 2 < T) issue(t + 2);
        cp_commit();

        const uint32_t sA = sb + (t % GNST) * GSTG;
        const uint32_t sB = sA + GASTG;

        #pragma unroll
        for (int ks = 0; ks < 4; ks++) {     // four k16 steps
            uint32_t af[2][4];
            #pragma unroll
            for (int mi = 0; mi < 2; mi++) {
                const int row = wm * 32 + mi * 16 + (lane & 7) + ((lane >> 3) & 1) * 8;
                const int ch  = 2 * ks + (lane >> 4);
                ldsm4(af[mi], sA + arow_off(row, ch));
            }
            uint32_t bf[4][4];
            #pragma unroll
            for (int n2 = 0; n2 < 4; n2++) {
                const int row = wn * 64 + n2 * 16 + (lane & 7) + ((lane >> 3) & 1) * 8;
                const int ch  = 2 * ks + (lane >> 4);
                ldsm4(bf[n2], sB + arow_off(row, ch));
            }
            #pragma unroll
            for (int ni = 0; ni < 8; ni++) {
                const uint32_t b0 = bf[ni >> 1][ni & 1];
                const uint32_t b1 = bf[ni >> 1][2 + (ni & 1)];
                #pragma unroll
                for (int mi = 0; mi < 2; mi++)
                    mma_f16(acc[mi][ni], af[mi], b0, b1);
            }
        }
        // next iteration's wait+sync guards buffer reuse
    }

    // epilogue
    #pragma unroll
    for (int mi = 0; mi < 2; mi++) {
        const int r0 = bm + wm * 32 + mi * 16 + g;
        #pragma unroll
        for (int ni = 0; ni < 8; ni++) {
            const int cn = bn + wn * 64 + ni * 8 + 2 * tg;
            const float bz0 = bias[cn], bz1 = bias[cn + 1];
            float v00 = acc[mi][ni][0] + bz0;
            float v01 = acc[mi][ni][1] + bz1;
            float v10 = acc[mi][ni][2] + bz0;
            float v11 = acc[mi][ni][3] + bz1;
            const long o0 = (long)r0 * N + cn;
            const long o1 = (long)(r0 + 8) * N + cn;
            if (EPI == 1) {
                v00 += R[o0]; v01 += R[o0 + 1];
                v10 += R[o1]; v11 += R[o1 + 1];
                float* C = (float*)Cout;
                *(float2*)&C[o0] = make_float2(v00, v01);
                *(float2*)&C[o1] = make_float2(v10, v11);
            } else {
                if (EPI == 2) {
                    v00 = 0.5f * v00 * (1.f + erff(v00 * 0.70710678118654752f));
                    v01 = 0.5f * v01 * (1.f + erff(v01 * 0.70710678118654752f));
                    v10 = 0.5f * v10 * (1.f + erff(v10 * 0.70710678118654752f));
                    v11 = 0.5f * v11 * (1.f + erff(v11 * 0.70710678118654752f));
                }
                __half* C = (__half*)Cout;
                *(__half2*)&C[o0] = __floats2half2_rn(v00, v01);
                *(__half2*)&C[o1] = __floats2half2_rn(v10, v11);
            }
        }
    }
}

// ---------------- Flash attention with fp16 HMMA ---------------------------
#define ASC 0.18033688011112042f   // 0.125 * log2(e)

__global__ __launch_bounds__(128)
void attn_kernel(const __half* __restrict__ qkv, __half* __restrict__ out)
{
    __shared__ __half sQ[64 * 64];
    __shared__ __half sK[2][64 * 64];
    __shared__ __half sV[2][64 * 64];

    const int qt = blockIdx.x, h = blockIdx.y, b = blockIdx.z;
    const int qb = qt * 64;
    const int tid = threadIdx.x;
    const int w = tid >> 5, lane = tid & 31;
    const int g = lane >> 2, tg = lane & 3;

    const uint32_t sQb = (uint32_t)__cvta_generic_to_shared(sQ);
    const uint32_t sKb[2] = { (uint32_t)__cvta_generic_to_shared(sK[0]),
                              (uint32_t)__cvta_generic_to_shared(sK[1]) };
    const uint32_t sVb[2] = { (uint32_t)__cvta_generic_to_shared(sV[0]),
                              (uint32_t)__cvta_generic_to_shared(sV[1]) };

    const long rowbase = (long)(b * SS);
    const __half* Qg = qkv + h * DD;
    const __half* Kg = qkv + EE + h * DD;
    const __half* Vg = qkv + 2 * EE + h * DD;

    const int tstart = (qb >= 193) ? 0 : (193 - qb + 63) / 64;
    const int tend   = min(8, (4351 - qb) / 64);

    #pragma unroll
    for (int i = 0; i < 4; i++) {
        const int id = tid + i * 128, r = id >> 3, c = id & 7;
        cp16(sQb + arow_off(r, c), (const char*)(Qg + (rowbase + qb + r) * C3) + c * 16);
    }
    auto issue = [&](int t, int buf) {
        const int kbase = qb - 256 + 64 * t;
        #pragma unroll
        for (int i = 0; i < 4; i++) {
            const int id = tid + i * 128, r = id >> 3, c = id & 7;
            int j = kbase + r; j = j < 0 ? 0 : (j >= SS ? SS - 1 : j);
            cp16(sKb[buf] + arow_off(r, c), (const char*)(Kg + (rowbase + j) * C3) + c * 16);
            cp16(sVb[buf] + arow_off(r, c), (const char*)(Vg + (rowbase + j) * C3) + c * 16);
        }
    };

    issue(tstart, 0);
    cp_commit();

    uint32_t aq[4][4];
    float acc_o[8][4] = {};
    float m0 = -1e30f, m1 = -1e30f, l0 = 0.f, l1 = 0.f;
    const int i0 = qb + w * 16 + g;
    const int i1 = i0 + 8;

    for (int t = tstart; t <= tend; t++) {
        const int buf = (t - tstart) & 1;
        if (t < tend) { issue(t + 1, buf ^ 1); cp_commit(); }
        if (t < tend) asm volatile("cp.async.wait_group 1;" ::: "memory");
        else          asm volatile("cp.async.wait_group 0;" ::: "memory");
        __syncthreads();

        if (t == tstart) {
            #pragma unroll
            for (int ks = 0; ks < 4; ks++) {
                const int row = w * 16 + (lane & 7) + ((lane >> 3) & 1) * 8;
                const int ch  = 2 * ks + (lane >> 4);
                ldsm4(aq[ks], sQb + arow_off(row, ch));
            }
        }

        const int kbase = qb - 256 + 64 * t;

        // ---- scores S = Q K^T ----
        float s[8][4] = {};
        #pragma unroll
        for (int ks = 0; ks < 4; ks++) {
            uint32_t bk[4][4];
            #pragma unroll
            for (int n2 = 0; n2 < 4; n2++) {
                const int row = n2 * 16 + (lane & 7) + ((lane >> 3) & 1) * 8;
                const int ch  = 2 * ks + (lane >> 4);
                ldsm4(bk[n2], sKb[buf] + arow_off(row, ch));
            }
            #pragma unroll
            for (int ni = 0; ni < 8; ni++)
                mma_f16(s[ni], aq[ks], bk[ni >> 1][ni & 1], bk[ni >> 1][2 + (ni & 1)]);
        }

        // ---- mask ----
        const bool masked = (t == 0) | (t == 8) | (kbase < 0) | (kbase + 63 >= SS);
        if (masked) {
            #pragma unroll
            for (int ni = 0; ni < 8; ni++) {
                #pragma unroll
                for (int c = 0; c < 2; c++) {
                    const int j = kbase + ni * 8 + 2 * tg + c;
                    const bool inseq = (j >= 0) & (j < SS);
                    if (!(inseq & (j >= i0 - WW) & (j <= i0 + WW))) s[ni][c]     = -1e30f;
                    if (!(inseq & (j >= i1 - WW) & (j <= i1 + WW))) s[ni][c + 2] = -1e30f;
                }
            }
        }

        // ---- online softmax ----
        float mx0 = s[0][0], mx1 = s[0][2];
        #pragma unroll
        for (int ni = 0; ni < 8; ni++) {
            mx0 = fmaxf(mx0, fmaxf(s[ni][0], s[ni][1]));
            mx1 = fmaxf(mx1, fmaxf(s[ni][2], s[ni][3]));
        }
        mx0 = fmaxf(mx0, __shfl_xor_sync(0xffffffffu, mx0, 1));
        mx0 = fmaxf(mx0, __shfl_xor_sync(0xffffffffu, mx0, 2));
        mx1 = fmaxf(mx1, __shfl_xor_sync(0xffffffffu, mx1, 1));
        mx1 = fmaxf(mx1, __shfl_xor_sync(0xffffffffu, mx1, 2));
        const float mn0 = fmaxf(m0, mx0), mn1 = fmaxf(m1, mx1);
        const float f0 = ex2((m0 - mn0) * ASC), f1 = ex2((m1 - mn1) * ASC);
        m0 = mn0; m1 = mn1;

        float ps0 = 0.f, ps1 = 0.f;
        #pragma unroll
        for (int ni = 0; ni < 8; ni++) {
            s[ni][0] = ex2((s[ni][0] - mn0) * ASC);
            s[ni][1] = ex2((s[ni][1] - mn0) * ASC);
            s[ni][2] = ex2((s[ni][2] - mn1) * ASC);
            s[ni][3] = ex2((s[ni][3] - mn1) * ASC);
            ps0 += s[ni][0] + s[ni][1];
            ps1 += s[ni][2] + s[ni][3];
        }
        // per-thread partials; quad-reduced once after the loop
        l0 = l0 * f0 + ps0;
        l1 = l1 * f1 + ps1;
        #pragma unroll
        for (int nd = 0; nd < 8; nd++) {
            acc_o[nd][0] *= f0; acc_o[nd][1] *= f0;
            acc_o[nd][2] *= f1; acc_o[nd][3] *= f1;
        }

        // ---- PV: O += P V ----
        #pragma unroll
        for (int kk = 0; kk < 4; kk++) {
            uint32_t pa[4];
            pa[0] = pack_h2(s[2*kk][0],   s[2*kk][1]);
            pa[1] = pack_h2(s[2*kk][2],   s[2*kk][3]);
            pa[2] = pack_h2(s[2*kk+1][0], s[2*kk+1][1]);
            pa[3] = pack_h2(s[2*kk+1][2], s[2*kk+1][3]);
            #pragma unroll
            for (int d2 = 0; d2 < 4; d2++) {
                uint32_t bv[4];
                const int row = kk * 16 + (lane & 7) + ((lane >> 3) & 1) * 8;
                const int ch  = 2 * d2 + (lane >> 4);
                ldsm4t(bv, sVb[buf] + arow_off(row, ch));
                mma_f16(acc_o[2 * d2],     pa, bv[0], bv[1]);
                mma_f16(acc_o[2 * d2 + 1], pa, bv[2], bv[3]);
            }
        }
        __syncthreads();
    }

    // reduce softmax denominator across the quad
    l0 += __shfl_xor_sync(0xffffffffu, l0, 1);
    l0 += __shfl_xor_sync(0xffffffffu, l0, 2);
    l1 += __shfl_xor_sync(0xffffffffu, l1, 1);
    l1 += __shfl_xor_sync(0xffffffffu, l1, 2);

    // ---- write out ----
    const float r0 = 1.f / l0, r1 = 1.f / l1;
    __half* o0 = out + (rowbase + i0) * EE + h * DD + 2 * tg;
    __half* o1 = out + (rowbase + i1) * EE + h * DD + 2 * tg;
    #pragma unroll
    for (int nd = 0; nd < 8; nd++) {
        *(__half2*)(o0 + nd * 8) = __floats2half2_rn(acc_o[nd][0] * r0, acc_o[nd][1] * r0);
        *(__half2*)(o1 + nd * 8) = __floats2half2_rn(acc_o[nd][2] * r1, acc_o[nd][3] * r1);
    }
}

// ---------------- launch ----------------
extern "C" void kernel_launch(void* const* d_in, const int* in_sizes, int n_in,
                              void* d_out, int out_size)
{
    const float* x        = (const float*)d_in[0];
    const float* ln1_g    = (const float*)d_in[1];
    const float* ln1_b    = (const float*)d_in[2];
    const float* c_attn_w = (const float*)d_in[3];
    const float* c_attn_b = (const float*)d_in[4];
    const float* c_proj_w = (const float*)d_in[5];
    const float* c_proj_b = (const float*)d_in[6];
    const float* ln2_g    = (const float*)d_in[7];
    const float* ln2_b    = (const float*)d_in[8];
    const float* fc_w     = (const float*)d_in[9];
    const float* fc_b     = (const float*)d_in[10];
    const float* proj2_w  = (const float*)d_in[11];
    const float* proj2_b  = (const float*)d_in[12];
    float* out = (float*)d_out;

    __half *h, *qkv, *attn, *ff;
    float *x1;
    __half *wT_attn, *wT_proj, *wT_fc, *wT_proj2;
    cudaGetSymbolAddress((void**)&h,    g_buf_h);
    cudaGetSymbolAddress((void**)&qkv,  g_buf_qkv);
    cudaGetSymbolAddress((void**)&attn, g_buf_attn);
    cudaGetSymbolAddress((void**)&x1,   g_buf_x1);
    cudaGetSymbolAddress((void**)&ff,   g_buf_ff);
    cudaGetSymbolAddress((void**)&wT_attn,  g_wT_attn);
    cudaGetSymbolAddress((void**)&wT_proj,  g_wT_proj);
    cudaGetSymbolAddress((void**)&wT_fc,    g_wT_fc);
    cudaGetSymbolAddress((void**)&wT_proj2, g_wT_proj2);

    cudaFuncSetAttribute(hgemm<0>, cudaFuncAttributeMaxDynamicSharedMemorySize, HG_SMEM);
    cudaFuncSetAttribute(hgemm<1>, cudaFuncAttributeMaxDynamicSharedMemorySize, HG_SMEM);
    cudaFuncSetAttribute(hgemm<2>, cudaFuncAttributeMaxDynamicSharedMemorySize, HG_SMEM);

    dim3 tb(32, 8);
    transpose_kernel<<<dim3(C3 / 32, EE / 32), tb>>>(c_attn_w, wT_attn, EE, C3);
    transpose_kernel<<<dim3(EE / 32, EE / 32), tb>>>(c_proj_w, wT_proj, EE, EE);
    transpose_kernel<<<dim3(E4 / 32, EE / 32), tb>>>(fc_w,     wT_fc,   EE, E4);
    transpose_kernel<<<dim3(EE / 32, E4 / 32), tb>>>(proj2_w,  wT_proj2, E4, EE);

    ln_kernel<<<ROWS, 256>>>(x, ln1_g, ln1_b, h);
    hgemm<0><<<dim3(C3 / 128, ROWS / 128), 256, HG_SMEM>>>(
        h, wT_attn, c_attn_b, nullptr, qkv, ROWS, C3, EE);
    attn_kernel<<<dim3(SS / 64, HH, BB), 128>>>(qkv, attn);
    hgemm<1><<<dim3(EE / 128, ROWS / 128), 256, HG_SMEM>>>(
        attn, wT_proj, c_proj_b, x, x1, ROWS, EE, EE);
    ln_kernel<<<ROWS, 256>>>(x1, ln2_g, ln2_b, h);
    hgemm<2><<<dim3(E4 / 128, ROWS / 128), 256, HG_SMEM>>>(
        h, wT_fc, fc_b, nullptr, ff, ROWS, E4, EE);
    hgemm<1><<<dim3(EE / 128, ROWS / 128), 256, HG_SMEM>>>(
        ff, wT_proj2, proj2_b, x1, out, ROWS, EE, E4);
}